// round 4
// baseline (speedup 1.0000x reference)
#include <cuda_runtime.h>
#include <cuda_bf16.h>

// Problem constants
#define BB   2
#define NN_  4096
#define NQv  1024
#define DIMv 512
#define HH   8
#define DHv  64
#define LMv  256
#define BHv  16
#define INNER 512

// ---------------- scratch (device globals; no allocation allowed) ----------------
__device__ float g_kv[(long)BB*NN_*1024];      // x @ W_kv : (b,n,1024)  [k | v]
__device__ float g_qmat[(long)BB*NQv*INNER];   // (q_input @ W_q) * scale
__device__ float g_kl[BHv*LMv*DHv];            // landmarks (bh, 256, 64)
__device__ float g_attn1[(long)BHv*NQv*LMv];   // softmax(q @ kl^T) (bh,1024,256)
__device__ float g_G[BHv*LMv*LMv];             // attn1^T attn1 (bh,256,256)
__device__ float g_qA[BHv*LMv*LMv];
__device__ float g_qB[BHv*LMv*LMv];
__device__ float g_M[BHv*LMv*LMv];
__device__ float g_r1[BHv*LMv*LMv];
__device__ float g_r2[BHv*LMv*LMv];
__device__ float g_Y[BHv*NQv*DHv];             // softmax(q k^T) @ v  (bh,1024,64)
__device__ float g_xty[BHv*LMv*DHv];           // attn1^T @ Y (bh,256,64)
__device__ float g_z2[BHv*LMv*DHv];            // q6 @ xty (bh,256,64)
__device__ float g_oc[(long)BB*NQv*INNER];     // gathered output (b, i, h*64+d)
__device__ float g_max[1];

// ---------------- high-throughput 128x128 SGEMM (contiguous row-major A,B,C) ------
__global__ __launch_bounds__(256) void sgemm128_kernel(
    const float* __restrict__ A, const float* __restrict__ B,
    const float* __restrict__ bias, float* __restrict__ C,
    int M, int N, int K, float alpha)
{
    __shared__ float As[2][8][132];
    __shared__ float Bs[2][8][128];

    int tid = threadIdx.x;
    int ty = tid >> 4, tx = tid & 15;
    int i0 = blockIdx.y * 128, j0 = blockIdx.x * 128;

    int arow = tid >> 1, akq = (tid & 1) * 4;
    int bkr = tid >> 5, bcq = (tid & 31) * 4;

    const float* Aptr = A + (long)(i0 + arow) * K + akq;
    const float* Bptr = B + (long)bkr * N + j0 + bcq;

    float4 av = *(const float4*)Aptr;
    float4 bv = *(const float4*)Bptr;
    As[0][akq + 0][arow] = av.x; As[0][akq + 1][arow] = av.y;
    As[0][akq + 2][arow] = av.z; As[0][akq + 3][arow] = av.w;
    *(float4*)&Bs[0][bkr][bcq] = bv;
    __syncthreads();

    float acc[8][8] = {};
    int T = K / 8;
    int buf = 0;
    for (int t = 0; t < T; t++) {
        if (t + 1 < T) {
            av = *(const float4*)(Aptr + (t + 1) * 8);
            bv = *(const float4*)(Bptr + (long)(t + 1) * 8 * N);
        }
        #pragma unroll
        for (int kk = 0; kk < 8; kk++) {
            float4 a0 = *(const float4*)&As[buf][kk][ty * 8];
            float4 a1 = *(const float4*)&As[buf][kk][ty * 8 + 4];
            float4 b0 = *(const float4*)&Bs[buf][kk][tx * 8];
            float4 b1 = *(const float4*)&Bs[buf][kk][tx * 8 + 4];
            float ar[8] = {a0.x, a0.y, a0.z, a0.w, a1.x, a1.y, a1.z, a1.w};
            float br[8] = {b0.x, b0.y, b0.z, b0.w, b1.x, b1.y, b1.z, b1.w};
            #pragma unroll
            for (int i = 0; i < 8; i++)
                #pragma unroll
                for (int j = 0; j < 8; j++)
                    acc[i][j] += ar[i] * br[j];
        }
        if (t + 1 < T) {
            int nb = buf ^ 1;
            As[nb][akq + 0][arow] = av.x; As[nb][akq + 1][arow] = av.y;
            As[nb][akq + 2][arow] = av.z; As[nb][akq + 3][arow] = av.w;
            *(float4*)&Bs[nb][bkr][bcq] = bv;
            __syncthreads();
            buf = nb;
        }
    }

    #pragma unroll
    for (int i = 0; i < 8; i++) {
        long row = i0 + ty * 8 + i;
        #pragma unroll
        for (int jq = 0; jq < 2; jq++) {
            int col = j0 + tx * 8 + jq * 4;
            float4 v;
            v.x = alpha * acc[i][jq * 4 + 0];
            v.y = alpha * acc[i][jq * 4 + 1];
            v.z = alpha * acc[i][jq * 4 + 2];
            v.w = alpha * acc[i][jq * 4 + 3];
            if (bias) {
                v.x += bias[col + 0]; v.y += bias[col + 1];
                v.z += bias[col + 2]; v.w += bias[col + 3];
            }
            *(float4*)&C[row * N + col] = v;
        }
    }
}

// ---------------- batched 128x64-tile GEMM, 8x4 per thread, double buffered ------
// TRANSA=0: A(i,k)=A[i*lda+k]; TRANSA=1: A(i,k)=A[k*lda+i]. B(k,j)=B[k*ldb+j].
// C(i,j) = alpha*acc + beta*D(i,j); C,D row-major ldc (D uses ldc too).
// batch z: zb=z>>3, zh=z&7. grid (N/64, M/128, nbatch). K%8==0.
template<int TRANSA>
__global__ __launch_bounds__(256) void gemm_tile_kernel(
    const float* __restrict__ A, const float* __restrict__ B,
    const float* __restrict__ D, float* __restrict__ C,
    int K, int lda, int ldb, int ldc,
    long sAo, long sAi, long sBo, long sBi, long sDo, long sDi, long sCo, long sCi,
    float alpha, float beta)
{
    int z = blockIdx.z; int zb = z >> 3, zh = z & 7;
    A += zb * sAo + zh * sAi;
    B += zb * sBo + zh * sBi;
    C += zb * sCo + zh * sCi;
    if (D) D += zb * sDo + zh * sDi;

    __shared__ float As[2][8][132];
    __shared__ float Bs[2][8][68];

    int tid = threadIdx.x;
    int ty = tid >> 4, tx = tid & 15;
    int i0 = blockIdx.y * 128, j0 = blockIdx.x * 64;

    // A loader
    int a_kr = tid >> 5;            // TRANSA: k row 0..7
    int a_iq = (tid & 31) * 4;      // TRANSA: i quad
    int a_row = tid >> 1;           // !TRANSA: i row 0..127
    int a_kq = (tid & 1) * 4;       // !TRANSA: k quad
    // B loader (first 128 threads)
    int b_kr = tid >> 4;            // 0..7 for tid<128
    int b_cq = (tid & 15) * 4;

    const float* Aptr = TRANSA ? (A + (long)a_kr * lda + i0 + a_iq)
                               : (A + (long)(i0 + a_row) * lda + a_kq);
    const float* Bptr = B + (long)b_kr * ldb + j0 + b_cq;

    float4 av = *(const float4*)Aptr;
    float4 bv = make_float4(0.f, 0.f, 0.f, 0.f);
    if (tid < 128) bv = *(const float4*)Bptr;

    if (TRANSA) {
        *(float4*)&As[0][a_kr][a_iq] = av;
    } else {
        As[0][a_kq + 0][a_row] = av.x; As[0][a_kq + 1][a_row] = av.y;
        As[0][a_kq + 2][a_row] = av.z; As[0][a_kq + 3][a_row] = av.w;
    }
    if (tid < 128) *(float4*)&Bs[0][b_kr][b_cq] = bv;
    __syncthreads();

    float acc[8][4] = {};
    int T = K / 8;
    int buf = 0;
    for (int t = 0; t < T; t++) {
        if (t + 1 < T) {
            av = TRANSA ? *(const float4*)(Aptr + (long)(t + 1) * 8 * lda)
                        : *(const float4*)(Aptr + (t + 1) * 8);
            if (tid < 128) bv = *(const float4*)(Bptr + (long)(t + 1) * 8 * ldb);
        }
        #pragma unroll
        for (int kk = 0; kk < 8; kk++) {
            float4 a0 = *(const float4*)&As[buf][kk][ty * 8];
            float4 a1 = *(const float4*)&As[buf][kk][ty * 8 + 4];
            float4 b0 = *(const float4*)&Bs[buf][kk][tx * 4];
            float ar[8] = {a0.x, a0.y, a0.z, a0.w, a1.x, a1.y, a1.z, a1.w};
            #pragma unroll
            for (int i = 0; i < 8; i++) {
                acc[i][0] += ar[i] * b0.x;
                acc[i][1] += ar[i] * b0.y;
                acc[i][2] += ar[i] * b0.z;
                acc[i][3] += ar[i] * b0.w;
            }
        }
        if (t + 1 < T) {
            int nb = buf ^ 1;
            if (TRANSA) {
                *(float4*)&As[nb][a_kr][a_iq] = av;
            } else {
                As[nb][a_kq + 0][a_row] = av.x; As[nb][a_kq + 1][a_row] = av.y;
                As[nb][a_kq + 2][a_row] = av.z; As[nb][a_kq + 3][a_row] = av.w;
            }
            if (tid < 128) *(float4*)&Bs[nb][b_kr][b_cq] = bv;
            __syncthreads();
            buf = nb;
        }
    }

    #pragma unroll
    for (int i = 0; i < 8; i++) {
        long row = i0 + ty * 8 + i;
        long off = row * ldc + j0 + tx * 4;
        float4 v;
        v.x = alpha * acc[i][0];
        v.y = alpha * acc[i][1];
        v.z = alpha * acc[i][2];
        v.w = alpha * acc[i][3];
        if (D) {
            float4 dv = *(const float4*)&D[off];
            v.x += beta * dv.x; v.y += beta * dv.y;
            v.z += beta * dv.z; v.w += beta * dv.w;
        }
        *(float4*)&C[off] = v;
    }
}

// ---------------- generic strided batched SGEMM (64x64 tiles) — sim1 only --------
__global__ __launch_bounds__(256) void sgemm_kernel(
    const float* __restrict__ A, const float* __restrict__ B,
    const float* __restrict__ D, const float* __restrict__ bias,
    float* __restrict__ C,
    int M, int N, int K,
    long sAo, long sAi, long sBo, long sBi, long sDo, long sDi, long sCo, long sCi,
    int a_rs, int a_cs, int b_rs, int b_cs, int c_ld,
    float alpha, float beta)
{
    int z = blockIdx.z; int zb = z >> 3, zh = z & 7;
    A += zb * sAo + zh * sAi;
    B += zb * sBo + zh * sBi;
    C += zb * sCo + zh * sCi;
    if (D) D += zb * sDo + zh * sDi;

    __shared__ float As[16][68];
    __shared__ float Bs[16][68];

    int tid = threadIdx.x;
    int ty = tid >> 4, tx = tid & 15;
    int i0 = blockIdx.y * 64, j0 = blockIdx.x * 64;

    float acc[4][4] = {};

    for (int k0 = 0; k0 < K; k0 += 16) {
        if (a_cs == 1) {
            #pragma unroll
            for (int t = tid; t < 64 * 16; t += 256) {
                int kk = t & 15, ii = t >> 4;
                As[kk][ii] = A[(long)(i0 + ii) * a_rs + (k0 + kk)];
            }
        } else {
            #pragma unroll
            for (int t = tid; t < 64 * 16; t += 256) {
                int ii = t & 63, kk = t >> 6;
                As[kk][ii] = A[(long)(i0 + ii) * a_rs + (long)(k0 + kk) * a_cs];
            }
        }
        if (b_cs == 1) {
            #pragma unroll
            for (int t = tid; t < 64 * 16; t += 256) {
                int jj = t & 63, kk = t >> 6;
                Bs[kk][jj] = B[(long)(k0 + kk) * b_rs + (j0 + jj)];
            }
        } else {
            #pragma unroll
            for (int t = tid; t < 64 * 16; t += 256) {
                int kk = t & 15, jj = t >> 4;
                Bs[kk][jj] = B[(long)(k0 + kk) * b_rs + (long)(j0 + jj) * b_cs];
            }
        }
        __syncthreads();

        #pragma unroll
        for (int kk = 0; kk < 16; kk++) {
            float4 av = *(const float4*)&As[kk][ty * 4];
            float4 bv = *(const float4*)&Bs[kk][tx * 4];
            float a0 = av.x, a1 = av.y, a2 = av.z, a3 = av.w;
            float b0 = bv.x, b1 = bv.y, b2 = bv.z, b3 = bv.w;
            acc[0][0] += a0 * b0; acc[0][1] += a0 * b1; acc[0][2] += a0 * b2; acc[0][3] += a0 * b3;
            acc[1][0] += a1 * b0; acc[1][1] += a1 * b1; acc[1][2] += a1 * b2; acc[1][3] += a1 * b3;
            acc[2][0] += a2 * b0; acc[2][1] += a2 * b1; acc[2][2] += a2 * b2; acc[2][3] += a2 * b3;
            acc[3][0] += a3 * b0; acc[3][1] += a3 * b1; acc[3][2] += a3 * b2; acc[3][3] += a3 * b3;
        }
        __syncthreads();
    }

    #pragma unroll
    for (int i = 0; i < 4; i++) {
        int row = i0 + ty * 4 + i;
        #pragma unroll
        for (int j = 0; j < 4; j++) {
            int col = j0 + tx * 4 + j;
            long off = (long)row * c_ld + col;
            float v = alpha * acc[i][j];
            if (D) v += beta * D[off];
            if (bias) v += bias[col];
            C[off] = v;
        }
    }
}

// ---------------- landmark pooling ----------------
__global__ void landmark_kernel(const float* __restrict__ kv, float* __restrict__ kl)
{
    int dd = threadIdx.x;           // 0..63
    int j  = blockIdx.x;            // 0..255
    int bh = blockIdx.y;            // 0..15
    int b = bh >> 3, h = bh & 7;
    const float* base = kv + (long)b * NN_ * 1024 + (long)(j * 16) * 1024 + h * DHv + dd;
    float s = 0.f;
    #pragma unroll
    for (int t = 0; t < 16; t++) s += base[(long)t * 1024];
    kl[((long)bh * LMv + j) * DHv + dd] = s;
}

// ---------------- row softmax over 256 columns (in place) ----------------
__global__ void softmax256_kernel(float* __restrict__ a)
{
    int row = blockIdx.x * 8 + (threadIdx.x >> 5);
    int lane = threadIdx.x & 31;
    float* p = a + (long)row * 256;
    float v[8];
    float mx = -1e30f;
    #pragma unroll
    for (int t = 0; t < 8; t++) { v[t] = p[lane + 32 * t]; mx = fmaxf(mx, v[t]); }
    #pragma unroll
    for (int o = 16; o > 0; o >>= 1) mx = fmaxf(mx, __shfl_xor_sync(0xffffffffu, mx, o));
    float s = 0.f;
    #pragma unroll
    for (int t = 0; t < 8; t++) { v[t] = __expf(v[t] - mx); s += v[t]; }
    #pragma unroll
    for (int o = 16; o > 0; o >>= 1) s += __shfl_xor_sync(0xffffffffu, s, o);
    float inv = 1.f / s;
    #pragma unroll
    for (int t = 0; t < 8; t++) p[lane + 32 * t] = v[t] * inv;
}

// ---------------- column sums of attn1 + global max ----------------
__global__ void initmax_kernel(float* m) { m[0] = 0.f; }

__global__ void colsummax_kernel(const float* __restrict__ a, float* __restrict__ dmax)
{
    int idx = blockIdx.x * blockDim.x + threadIdx.x;    // 0..4095
    int bh = idx >> 8, j = idx & 255;
    const float* p = a + (long)bh * NQv * LMv + j;
    float s = 0.f;
    for (int i = 0; i < NQv; i++) s += p[(long)i * 256];
    atomicMax((int*)dmax, __float_as_int(s));
}

// ---------------- q0 = alpha * I ----------------
__global__ void qinit_kernel(float* __restrict__ q, const float* __restrict__ dmax)
{
    long idx = (long)blockIdx.x * 256 + threadIdx.x;    // 16*256*256
    int r = (int)((idx >> 8) & 255), c = (int)(idx & 255);
    q[idx] = (r == c) ? (1.0f / dmax[0]) : 0.f;
}

// ---------------- flash attention v2: 128q x 128k tiles, 8x8 / 8x4 per thread ----
// grid (NQ/128, 16), 256 threads, smem = (2*64*132 + 128*68 + 128*132) * 4 bytes
#define FLASH2_SMEM ((2*64*132 + 128*68 + 128*132) * 4)
__global__ __launch_bounds__(256) void flash2_kernel(
    const float* __restrict__ qmat, const float* __restrict__ kv, float* __restrict__ Y)
{
    int bh = blockIdx.y; int b = bh >> 3, h = bh & 7;
    const float* qb = qmat + (long)b * NQv * INNER + h * DHv;
    const float* kb = kv + (long)b * NN_ * 1024 + h * DHv;
    const float* vb = kb + 512;
    int i0 = blockIdx.x * 128;

    extern __shared__ float sm[];
    float (*Qts)[132] = (float(*)[132])sm;                          // [64][132] Q^T
    float (*Kts)[132] = (float(*)[132])(sm + 64 * 132);             // [64][132] K^T
    float (*Vs)[68]   = (float(*)[68]) (sm + 2 * 64 * 132);         // [128][68] V
    float (*Ps)[132]  = (float(*)[132])(sm + 2 * 64 * 132 + 128 * 68); // [128][132] P

    int tid = threadIdx.x, ty = tid >> 4, tx = tid & 15;

    for (int t = tid; t < 128 * 64; t += 256) {
        int r = t >> 6, dd = t & 63;
        Qts[dd][r] = qb[(long)(i0 + r) * INNER + dd];
    }

    float m[8], l[8], o[8][4];
    #pragma unroll
    for (int i = 0; i < 8; i++) {
        m[i] = -1e30f; l[i] = 0.f;
        o[i][0] = o[i][1] = o[i][2] = o[i][3] = 0.f;
    }

    for (int c0 = 0; c0 < NN_; c0 += 128) {
        for (int t = tid; t < 128 * 64; t += 256) {
            int r = t >> 6, dd = t & 63;
            Kts[dd][r] = kb[(long)(c0 + r) * 1024 + dd];
            Vs[r][dd]  = vb[(long)(c0 + r) * 1024 + dd];
        }
        __syncthreads();

        float s[8][8] = {};
        #pragma unroll
        for (int d = 0; d < 64; d++) {
            float4 a0 = *(const float4*)&Qts[d][ty * 8];
            float4 a1 = *(const float4*)&Qts[d][ty * 8 + 4];
            float4 b0 = *(const float4*)&Kts[d][tx * 8];
            float4 b1 = *(const float4*)&Kts[d][tx * 8 + 4];
            float ar[8] = {a0.x, a0.y, a0.z, a0.w, a1.x, a1.y, a1.z, a1.w};
            float br[8] = {b0.x, b0.y, b0.z, b0.w, b1.x, b1.y, b1.z, b1.w};
            #pragma unroll
            for (int i = 0; i < 8; i++)
                #pragma unroll
                for (int j = 0; j < 8; j++)
                    s[i][j] += ar[i] * br[j];
        }

        #pragma unroll
        for (int i = 0; i < 8; i++) {
            float rm = s[i][0];
            #pragma unroll
            for (int j = 1; j < 8; j++) rm = fmaxf(rm, s[i][j]);
            #pragma unroll
            for (int off = 8; off > 0; off >>= 1) rm = fmaxf(rm, __shfl_xor_sync(0xffffffffu, rm, off));
            float mn = fmaxf(m[i], rm);
            float corr = __expf(m[i] - mn);
            float rs = 0.f;
            #pragma unroll
            for (int j = 0; j < 8; j++) { s[i][j] = __expf(s[i][j] - mn); rs += s[i][j]; }
            #pragma unroll
            for (int off = 8; off > 0; off >>= 1) rs += __shfl_xor_sync(0xffffffffu, rs, off);
            l[i] = l[i] * corr + rs;
            o[i][0] *= corr; o[i][1] *= corr; o[i][2] *= corr; o[i][3] *= corr;
            m[i] = mn;
            *(float4*)&Ps[ty * 8 + i][tx * 8]     = make_float4(s[i][0], s[i][1], s[i][2], s[i][3]);
            *(float4*)&Ps[ty * 8 + i][tx * 8 + 4] = make_float4(s[i][4], s[i][5], s[i][6], s[i][7]);
        }
        __syncthreads();

        #pragma unroll 4
        for (int c = 0; c < 128; c += 4) {
            float4 v0 = *(const float4*)&Vs[c + 0][tx * 4];
            float4 v1 = *(const float4*)&Vs[c + 1][tx * 4];
            float4 v2 = *(const float4*)&Vs[c + 2][tx * 4];
            float4 v3 = *(const float4*)&Vs[c + 3][tx * 4];
            #pragma unroll
            for (int i = 0; i < 8; i++) {
                float4 p = *(const float4*)&Ps[ty * 8 + i][c];
                o[i][0] += p.x * v0.x + p.y * v1.x + p.z * v2.x + p.w * v3.x;
                o[i][1] += p.x * v0.y + p.y * v1.y + p.z * v2.y + p.w * v3.y;
                o[i][2] += p.x * v0.z + p.y * v1.z + p.z * v2.z + p.w * v3.z;
                o[i][3] += p.x * v0.w + p.y * v1.w + p.z * v2.w + p.w * v3.w;
            }
        }
        __syncthreads();
    }

    #pragma unroll
    for (int i = 0; i < 8; i++) {
        float inv = 1.f / l[i];
        float4 v = make_float4(o[i][0] * inv, o[i][1] * inv, o[i][2] * inv, o[i][3] * inv);
        *(float4*)&Y[((long)bh * NQv + (i0 + ty * 8 + i)) * DHv + tx * 4] = v;
    }
}

// ---------------- host launch ----------------
static void* sym(const void* s) { void* p = nullptr; cudaGetSymbolAddress(&p, s); return p; }

extern "C" void kernel_launch(void* const* d_in, const int* in_sizes, int n_in,
                              void* d_out, int out_size)
{
    const float* x      = (const float*)d_in[0];
    const float* qin    = (const float*)d_in[1];
    const float* W_kv   = (const float*)d_in[2];
    const float* W_q    = (const float*)d_in[3];
    const float* W_out  = (const float*)d_in[4];
    const float* b_out  = (const float*)d_in[5];
    float* out = (float*)d_out;

    float* kv    = (float*)sym(g_kv);
    float* qmat  = (float*)sym(g_qmat);
    float* kl    = (float*)sym(g_kl);
    float* attn1 = (float*)sym(g_attn1);
    float* G     = (float*)sym(g_G);
    float* qA    = (float*)sym(g_qA);
    float* qB    = (float*)sym(g_qB);
    float* Mb    = (float*)sym(g_M);
    float* r1    = (float*)sym(g_r1);
    float* r2    = (float*)sym(g_r2);
    float* Yb    = (float*)sym(g_Y);
    float* xty   = (float*)sym(g_xty);
    float* z2    = (float*)sym(g_z2);
    float* oc    = (float*)sym(g_oc);
    float* dmax  = (float*)sym(g_max);

    // one-time init (first call is the uncaptured correctness run)
    static bool init_done = false;
    static cudaStream_t s1;
    static cudaEvent_t eIn, eKV, eQ, eAttn, eY;
    if (!init_done) {
        cudaFuncSetAttribute(flash2_kernel, cudaFuncAttributeMaxDynamicSharedMemorySize, FLASH2_SMEM);
        cudaStreamCreateWithFlags(&s1, cudaStreamNonBlocking);
        cudaEventCreateWithFlags(&eIn,   cudaEventDisableTiming);
        cudaEventCreateWithFlags(&eKV,   cudaEventDisableTiming);
        cudaEventCreateWithFlags(&eQ,    cudaEventDisableTiming);
        cudaEventCreateWithFlags(&eAttn, cudaEventDisableTiming);
        cudaEventCreateWithFlags(&eY,    cudaEventDisableTiming);
        init_done = true;
    }

    const float scale = 0.125f;    // 64^-0.5
    const long PQ = (long)LMv * LMv;         // 65536
    const long A1 = (long)NQv * LMv;         // 262144
    const long YS = (long)NQv * DHv;         // 65536
    const long XS = (long)LMv * DHv;         // 16384

    // fork point
    cudaEventRecord(eIn, 0);
    cudaStreamWaitEvent(s1, eIn, 0);

    // s0: kv = x @ W_kv   (8192 x 1024 x 512)
    sgemm128_kernel<<<dim3(1024/128, 8192/128, 1), 256, 0, 0>>>(
        x, W_kv, nullptr, kv, 8192, 1024, 512, 1.f);

    // s1: qmat = scale * (q_input @ W_q)  (2048 x 512 x 512)
    sgemm128_kernel<<<dim3(512/128, 2048/128, 1), 256, 0, s1>>>(
        qin, W_q, nullptr, qmat, 2048, 512, 512, scale);
    cudaEventRecord(eQ, s1);

    // s0: landmarks (needs kv)
    landmark_kernel<<<dim3(256, 16), 64, 0, 0>>>(kv, kl);
    cudaEventRecord(eKV, 0);     // kv (and landmarks) ready

    // s0: sim1 = q @ kl^T per bh (needs qmat)
    cudaStreamWaitEvent(0, eQ, 0);
    sgemm_kernel<<<dim3(256/64, 1024/64, 16), 256, 0, 0>>>(
        qmat, kl, nullptr, nullptr, attn1, 1024, 256, 64,
        (long)NQv*INNER, 64,  8*XS, XS,  0,0,  8*A1, A1,
        512,1, 1,64, 256, 1.f, 0.f);

    // s0: softmax rows (in place) -> attn1
    softmax256_kernel<<<(BHv * NQv) / 8, 256, 0, 0>>>(attn1);
    cudaEventRecord(eAttn, 0);

    // ---- s1 branch: flash (needs kv+qmat), then xty (needs attn1+Y) ----
    cudaStreamWaitEvent(s1, eKV, 0);
    flash2_kernel<<<dim3(NQv / 128, 16), 256, FLASH2_SMEM, s1>>>(qmat, kv, Yb);
    cudaStreamWaitEvent(s1, eAttn, 0);
    // xty = attn1^T @ Y per bh (256 x 64 x 1024)
    gemm_tile_kernel<1><<<dim3(1, 2, 16), 256, 0, s1>>>(
        attn1, Yb, nullptr, xty, 1024, 256, 64, 64,
        8*A1, A1, 8*YS, YS, 0,0, 8*XS, XS, 1.f, 0.f);
    cudaEventRecord(eY, s1);

    // ---- s0 branch: G + alpha + pinv chain ----
    // G = attn1^T @ attn1 per bh (256 x 256 x 1024)
    gemm_tile_kernel<1><<<dim3(4, 2, 16), 256, 0, 0>>>(
        attn1, attn1, nullptr, G, 1024, 256, 256, 256,
        8*A1, A1, 8*A1, A1, 0,0, 8*PQ, PQ, 1.f, 0.f);

    initmax_kernel<<<1, 1, 0, 0>>>(dmax);
    colsummax_kernel<<<16, 256, 0, 0>>>(attn1, dmax);
    qinit_kernel<<<(BHv * 256 * 256) / 256, 256, 0, 0>>>(qA, dmax);

    // 6 pinv iterations in Gram space (all 256x256x256, batch 16)
    float* qc = qA; float* qn = qB;
    for (int it = 0; it < 6; it++) {
        // M = q @ G
        gemm_tile_kernel<0><<<dim3(4, 2, 16), 256, 0, 0>>>(
            qc, G, nullptr, Mb, 256, 256, 256, 256,
            8*PQ, PQ, 8*PQ, PQ, 0,0, 8*PQ, PQ, 1.f, 0.f);
        // r1 = 7q - M@q
        gemm_tile_kernel<0><<<dim3(4, 2, 16), 256, 0, 0>>>(
            Mb, qc, qc, r1, 256, 256, 256, 256,
            8*PQ, PQ, 8*PQ, PQ, 8*PQ, PQ, 8*PQ, PQ, -1.f, 7.f);
        // r2 = 15q - M@r1
        gemm_tile_kernel<0><<<dim3(4, 2, 16), 256, 0, 0>>>(
            Mb, r1, qc, r2, 256, 256, 256, 256,
            8*PQ, PQ, 8*PQ, PQ, 8*PQ, PQ, 8*PQ, PQ, -1.f, 15.f);
        // qn = 3.25q - 0.25*M@r2
        gemm_tile_kernel<0><<<dim3(4, 2, 16), 256, 0, 0>>>(
            Mb, r2, qc, qn, 256, 256, 256, 256,
            8*PQ, PQ, 8*PQ, PQ, 8*PQ, PQ, 8*PQ, PQ, -0.25f, 3.25f);
        float* t = qc; qc = qn; qn = t;
    }
    // final q in qc

    // join: z2 needs q6 (s0) and xty (s1)
    cudaStreamWaitEvent(0, eY, 0);

    // z2 = q6 @ xty per bh (256 x 64 x 256)
    gemm_tile_kernel<0><<<dim3(1, 2, 16), 256, 0, 0>>>(
        qc, xty, nullptr, z2, 256, 256, 64, 64,
        8*PQ, PQ, 8*XS, XS, 0,0, 8*XS, XS, 1.f, 0.f);

    // O = attn1 @ z2 per bh -> gather into oc[b][i][h*64+dd]  (1024 x 64 x 256)
    gemm_tile_kernel<0><<<dim3(1, 8, 16), 256, 0, 0>>>(
        attn1, z2, nullptr, oc, 256, 256, 64, 512,
        8*A1, A1, 8*XS, XS, 0,0, (long)NQv*INNER, 64, 1.f, 0.f);

    // out = oc @ W_out + b_out (2048 x 512 x 512)
    sgemm128_kernel<<<dim3(512/128, 2048/128, 1), 256, 0, 0>>>(
        oc, W_out, b_out, out, 2048, 512, 512, 1.f);
}

// round 7
// speedup vs baseline: 1.0735x; 1.0735x over previous
#include <cuda_runtime.h>
#include <cuda_bf16.h>

// Problem constants
#define BB   2
#define NN_  4096
#define NQv  1024
#define DIMv 512
#define HH   8
#define DHv  64
#define LMv  256
#define BHv  16
#define INNER 512

typedef unsigned long long u64;

// ---------------- f32x2 packed helpers (Blackwell) ----------------
__device__ __forceinline__ void ffma2(u64 &d, u64 a, u64 b) {
    asm("fma.rn.f32x2 %0, %1, %2, %0;" : "+l"(d) : "l"(a), "l"(b));
}
__device__ __forceinline__ u64 pack2(float x, float y) {
    u64 r; asm("mov.b64 %0, {%1, %2};" : "=l"(r) : "f"(x), "f"(y)); return r;
}
__device__ __forceinline__ u64 dup2(float x) { return pack2(x, x); }
__device__ __forceinline__ float2 unpack2(u64 v) {
    float lo, hi; asm("mov.b64 {%0, %1}, %2;" : "=f"(lo), "=f"(hi) : "l"(v));
    return make_float2(lo, hi);
}
__device__ __forceinline__ void fmul2(u64 &d, u64 a) {
    asm("mul.rn.f32x2 %0, %0, %1;" : "+l"(d) : "l"(a));
}

// ---------------- scratch (device globals; no allocation allowed) ----------------
__device__ float g_kv[(long)BB*NN_*1024];
__device__ float g_qmat[(long)BB*NQv*INNER];
__device__ float g_kl[BHv*LMv*DHv];
__device__ float g_attn1[(long)BHv*NQv*LMv];
__device__ float g_G[BHv*LMv*LMv];
__device__ float g_qA[BHv*LMv*LMv];
__device__ float g_qB[BHv*LMv*LMv];
__device__ float g_M[BHv*LMv*LMv];
__device__ float g_r1[BHv*LMv*LMv];
__device__ float g_r2[BHv*LMv*LMv];
__device__ float g_Y[BHv*NQv*DHv];
__device__ float g_xty[BHv*LMv*DHv];
__device__ float g_z2[BHv*LMv*DHv];
__device__ float g_oc[(long)BB*NQv*INNER];
__device__ float g_max[1];

// ---------------- 128x128 SGEMM, f32x2 accumulators ----------------
// C = alpha * A@B (+ bias). A: MxK ld=K, B: KxN ld=N, C row-major ld=N.
__global__ __launch_bounds__(256) void sgemm128_kernel(
    const float* __restrict__ A, const float* __restrict__ B,
    const float* __restrict__ bias, float* __restrict__ C,
    int M, int N, int K, float alpha)
{
    __shared__ float As[2][8][132];
    __shared__ float Bs[2][8][128];

    int tid = threadIdx.x;
    int ty = tid >> 4, tx = tid & 15;
    int i0 = blockIdx.y * 128, j0 = blockIdx.x * 128;

    int arow = tid >> 1, akq = (tid & 1) * 4;
    int bkr = tid >> 5, bcq = (tid & 31) * 4;

    const float* Aptr = A + (long)(i0 + arow) * K + akq;
    const float* Bptr = B + (long)bkr * N + j0 + bcq;

    float4 av = *(const float4*)Aptr;
    float4 bv = *(const float4*)Bptr;
    As[0][akq + 0][arow] = av.x; As[0][akq + 1][arow] = av.y;
    As[0][akq + 2][arow] = av.z; As[0][akq + 3][arow] = av.w;
    *(float4*)&Bs[0][bkr][bcq] = bv;
    __syncthreads();

    u64 acc2[4][8] = {};   // i-pairs x 8 cols
    int T = K / 8;
    int buf = 0;
    for (int t = 0; t < T; t++) {
        if (t + 1 < T) {
            av = *(const float4*)(Aptr + (t + 1) * 8);
            bv = *(const float4*)(Bptr + (long)(t + 1) * 8 * N);
        }
        #pragma unroll
        for (int kk = 0; kk < 8; kk++) {
            ulonglong2 a01 = *(const ulonglong2*)&As[buf][kk][ty * 8];
            ulonglong2 a23 = *(const ulonglong2*)&As[buf][kk][ty * 8 + 4];
            float4 b0 = *(const float4*)&Bs[buf][kk][tx * 8];
            float4 b1 = *(const float4*)&Bs[buf][kk][tx * 8 + 4];
            u64 ap[4] = {a01.x, a01.y, a23.x, a23.y};
            u64 bd[8] = {dup2(b0.x), dup2(b0.y), dup2(b0.z), dup2(b0.w),
                         dup2(b1.x), dup2(b1.y), dup2(b1.z), dup2(b1.w)};
            #pragma unroll
            for (int p = 0; p < 4; p++)
                #pragma unroll
                for (int j = 0; j < 8; j++)
                    ffma2(acc2[p][j], ap[p], bd[j]);
        }
        if (t + 1 < T) {
            int nb = buf ^ 1;
            As[nb][akq + 0][arow] = av.x; As[nb][akq + 1][arow] = av.y;
            As[nb][akq + 2][arow] = av.z; As[nb][akq + 3][arow] = av.w;
            *(float4*)&Bs[nb][bkr][bcq] = bv;
            __syncthreads();
            buf = nb;
        }
    }

    #pragma unroll
    for (int p = 0; p < 4; p++) {
        float2 c[8];
        #pragma unroll
        for (int j = 0; j < 8; j++) c[j] = unpack2(acc2[p][j]);
        #pragma unroll
        for (int half = 0; half < 2; half++) {
            long row = i0 + ty * 8 + 2 * p + half;
            #pragma unroll
            for (int jq = 0; jq < 2; jq++) {
                int col = j0 + tx * 8 + jq * 4;
                float4 v;
                v.x = alpha * (half ? c[jq*4+0].y : c[jq*4+0].x);
                v.y = alpha * (half ? c[jq*4+1].y : c[jq*4+1].x);
                v.z = alpha * (half ? c[jq*4+2].y : c[jq*4+2].x);
                v.w = alpha * (half ? c[jq*4+3].y : c[jq*4+3].x);
                if (bias) {
                    v.x += bias[col + 0]; v.y += bias[col + 1];
                    v.z += bias[col + 2]; v.w += bias[col + 3];
                }
                *(float4*)&C[row * N + col] = v;
            }
        }
    }
}

// ---------------- batched 128x64-tile GEMM, f32x2, double buffered ----------------
// TRANSA=0: A(i,k)=A[i*lda+k]; TRANSA=1: A(i,k)=A[k*lda+i]. B(k,j)=B[k*ldb+j].
// C(i,j) = alpha*acc + beta*D(i,j). grid (N/64, M/128, nbatch). K%8==0.
template<int TRANSA>
__global__ __launch_bounds__(256) void gemm_tile_kernel(
    const float* __restrict__ A, const float* __restrict__ B,
    const float* __restrict__ D, float* __restrict__ C,
    int K, int lda, int ldb, int ldc,
    long sAo, long sAi, long sBo, long sBi, long sDo, long sDi, long sCo, long sCi,
    float alpha, float beta)
{
    int z = blockIdx.z; int zb = z >> 3, zh = z & 7;
    A += zb * sAo + zh * sAi;
    B += zb * sBo + zh * sBi;
    C += zb * sCo + zh * sCi;
    if (D) D += zb * sDo + zh * sDi;

    __shared__ float As[2][8][132];
    __shared__ float Bs[2][8][68];

    int tid = threadIdx.x;
    int ty = tid >> 4, tx = tid & 15;
    int i0 = blockIdx.y * 128, j0 = blockIdx.x * 64;

    int a_kr = tid >> 5;
    int a_iq = (tid & 31) * 4;
    int a_row = tid >> 1;
    int a_kq = (tid & 1) * 4;
    int b_kr = tid >> 4;
    int b_cq = (tid & 15) * 4;

    const float* Aptr = TRANSA ? (A + (long)a_kr * lda + i0 + a_iq)
                               : (A + (long)(i0 + a_row) * lda + a_kq);
    const float* Bptr = B + (long)b_kr * ldb + j0 + b_cq;

    float4 av = *(const float4*)Aptr;
    float4 bv = make_float4(0.f, 0.f, 0.f, 0.f);
    if (tid < 128) bv = *(const float4*)Bptr;

    if (TRANSA) {
        *(float4*)&As[0][a_kr][a_iq] = av;
    } else {
        As[0][a_kq + 0][a_row] = av.x; As[0][a_kq + 1][a_row] = av.y;
        As[0][a_kq + 2][a_row] = av.z; As[0][a_kq + 3][a_row] = av.w;
    }
    if (tid < 128) *(float4*)&Bs[0][b_kr][b_cq] = bv;
    __syncthreads();

    u64 acc2[4][4] = {};   // i-pairs x 4 cols
    int T = K / 8;
    int buf = 0;
    for (int t = 0; t < T; t++) {
        if (t + 1 < T) {
            av = TRANSA ? *(const float4*)(Aptr + (long)(t + 1) * 8 * lda)
                        : *(const float4*)(Aptr + (t + 1) * 8);
            if (tid < 128) bv = *(const float4*)(Bptr + (long)(t + 1) * 8 * ldb);
        }
        #pragma unroll
        for (int kk = 0; kk < 8; kk++) {
            ulonglong2 a01 = *(const ulonglong2*)&As[buf][kk][ty * 8];
            ulonglong2 a23 = *(const ulonglong2*)&As[buf][kk][ty * 8 + 4];
            float4 b0 = *(const float4*)&Bs[buf][kk][tx * 4];
            u64 ap[4] = {a01.x, a01.y, a23.x, a23.y};
            u64 bd[4] = {dup2(b0.x), dup2(b0.y), dup2(b0.z), dup2(b0.w)};
            #pragma unroll
            for (int p = 0; p < 4; p++) {
                ffma2(acc2[p][0], ap[p], bd[0]);
                ffma2(acc2[p][1], ap[p], bd[1]);
                ffma2(acc2[p][2], ap[p], bd[2]);
                ffma2(acc2[p][3], ap[p], bd[3]);
            }
        }
        if (t + 1 < T) {
            int nb = buf ^ 1;
            if (TRANSA) {
                *(float4*)&As[nb][a_kr][a_iq] = av;
            } else {
                As[nb][a_kq + 0][a_row] = av.x; As[nb][a_kq + 1][a_row] = av.y;
                As[nb][a_kq + 2][a_row] = av.z; As[nb][a_kq + 3][a_row] = av.w;
            }
            if (tid < 128) *(float4*)&Bs[nb][b_kr][b_cq] = bv;
            __syncthreads();
            buf = nb;
        }
    }

    #pragma unroll
    for (int p = 0; p < 4; p++) {
        float2 c0 = unpack2(acc2[p][0]);
        float2 c1 = unpack2(acc2[p][1]);
        float2 c2 = unpack2(acc2[p][2]);
        float2 c3 = unpack2(acc2[p][3]);
        #pragma unroll
        for (int half = 0; half < 2; half++) {
            long row = i0 + ty * 8 + 2 * p + half;
            long off = row * ldc + j0 + tx * 4;
            float4 v;
            v.x = alpha * (half ? c0.y : c0.x);
            v.y = alpha * (half ? c1.y : c1.x);
            v.z = alpha * (half ? c2.y : c2.x);
            v.w = alpha * (half ? c3.y : c3.x);
            if (D) {
                float4 dv = *(const float4*)&D[off];
                v.x += beta * dv.x; v.y += beta * dv.y;
                v.z += beta * dv.z; v.w += beta * dv.w;
            }
            *(float4*)&C[off] = v;
        }
    }
}

// ---------------- generic strided batched SGEMM (64x64 tiles) — sim1 only --------
__global__ __launch_bounds__(256) void sgemm_kernel(
    const float* __restrict__ A, const float* __restrict__ B,
    const float* __restrict__ D, const float* __restrict__ bias,
    float* __restrict__ C,
    int M, int N, int K,
    long sAo, long sAi, long sBo, long sBi, long sDo, long sDi, long sCo, long sCi,
    int a_rs, int a_cs, int b_rs, int b_cs, int c_ld,
    float alpha, float beta)
{
    int z = blockIdx.z; int zb = z >> 3, zh = z & 7;
    A += zb * sAo + zh * sAi;
    B += zb * sBo + zh * sBi;
    C += zb * sCo + zh * sCi;
    if (D) D += zb * sDo + zh * sDi;

    __shared__ float As[16][68];
    __shared__ float Bs[16][68];

    int tid = threadIdx.x;
    int ty = tid >> 4, tx = tid & 15;
    int i0 = blockIdx.y * 64, j0 = blockIdx.x * 64;

    float acc[4][4] = {};

    for (int k0 = 0; k0 < K; k0 += 16) {
        if (a_cs == 1) {
            #pragma unroll
            for (int t = tid; t < 64 * 16; t += 256) {
                int kk = t & 15, ii = t >> 4;
                As[kk][ii] = A[(long)(i0 + ii) * a_rs + (k0 + kk)];
            }
        } else {
            #pragma unroll
            for (int t = tid; t < 64 * 16; t += 256) {
                int ii = t & 63, kk = t >> 6;
                As[kk][ii] = A[(long)(i0 + ii) * a_rs + (long)(k0 + kk) * a_cs];
            }
        }
        if (b_cs == 1) {
            #pragma unroll
            for (int t = tid; t < 64 * 16; t += 256) {
                int jj = t & 63, kk = t >> 6;
                Bs[kk][jj] = B[(long)(k0 + kk) * b_rs + (j0 + jj)];
            }
        } else {
            #pragma unroll
            for (int t = tid; t < 64 * 16; t += 256) {
                int kk = t & 15, jj = t >> 4;
                Bs[kk][jj] = B[(long)(k0 + kk) * b_rs + (long)(j0 + jj) * b_cs];
            }
        }
        __syncthreads();

        #pragma unroll
        for (int kk = 0; kk < 16; kk++) {
            float4 av = *(const float4*)&As[kk][ty * 4];
            float4 bv = *(const float4*)&Bs[kk][tx * 4];
            float a0 = av.x, a1 = av.y, a2 = av.z, a3 = av.w;
            float b0 = bv.x, b1 = bv.y, b2 = bv.z, b3 = bv.w;
            acc[0][0] += a0 * b0; acc[0][1] += a0 * b1; acc[0][2] += a0 * b2; acc[0][3] += a0 * b3;
            acc[1][0] += a1 * b0; acc[1][1] += a1 * b1; acc[1][2] += a1 * b2; acc[1][3] += a1 * b3;
            acc[2][0] += a2 * b0; acc[2][1] += a2 * b1; acc[2][2] += a2 * b2; acc[2][3] += a2 * b3;
            acc[3][0] += a3 * b0; acc[3][1] += a3 * b1; acc[3][2] += a3 * b2; acc[3][3] += a3 * b3;
        }
        __syncthreads();
    }

    #pragma unroll
    for (int i = 0; i < 4; i++) {
        int row = i0 + ty * 4 + i;
        #pragma unroll
        for (int j = 0; j < 4; j++) {
            int col = j0 + tx * 4 + j;
            long off = (long)row * c_ld + col;
            float v = alpha * acc[i][j];
            if (D) v += beta * D[off];
            if (bias) v += bias[col];
            C[off] = v;
        }
    }
}

// ---------------- landmark pooling ----------------
__global__ void landmark_kernel(const float* __restrict__ kv, float* __restrict__ kl)
{
    int dd = threadIdx.x;
    int j  = blockIdx.x;
    int bh = blockIdx.y;
    int b = bh >> 3, h = bh & 7;
    const float* base = kv + (long)b * NN_ * 1024 + (long)(j * 16) * 1024 + h * DHv + dd;
    float s = 0.f;
    #pragma unroll
    for (int t = 0; t < 16; t++) s += base[(long)t * 1024];
    kl[((long)bh * LMv + j) * DHv + dd] = s;
}

// ---------------- row softmax over 256 columns (in place) ----------------
__global__ void softmax256_kernel(float* __restrict__ a)
{
    int row = blockIdx.x * 8 + (threadIdx.x >> 5);
    int lane = threadIdx.x & 31;
    float* p = a + (long)row * 256;
    float v[8];
    float mx = -1e30f;
    #pragma unroll
    for (int t = 0; t < 8; t++) { v[t] = p[lane + 32 * t]; mx = fmaxf(mx, v[t]); }
    #pragma unroll
    for (int o = 16; o > 0; o >>= 1) mx = fmaxf(mx, __shfl_xor_sync(0xffffffffu, mx, o));
    float s = 0.f;
    #pragma unroll
    for (int t = 0; t < 8; t++) { v[t] = __expf(v[t] - mx); s += v[t]; }
    #pragma unroll
    for (int o = 16; o > 0; o >>= 1) s += __shfl_xor_sync(0xffffffffu, s, o);
    float inv = 1.f / s;
    #pragma unroll
    for (int t = 0; t < 8; t++) p[lane + 32 * t] = v[t] * inv;
}

// ---------------- column sums of attn1 + global max ----------------
__global__ void initmax_kernel(float* m) { m[0] = 0.f; }

__global__ void colsummax_kernel(const float* __restrict__ a, float* __restrict__ dmax)
{
    int idx = blockIdx.x * blockDim.x + threadIdx.x;
    int bh = idx >> 8, j = idx & 255;
    const float* p = a + (long)bh * NQv * LMv + j;
    float s = 0.f;
    for (int i = 0; i < NQv; i++) s += p[(long)i * 256];
    atomicMax((int*)dmax, __float_as_int(s));
}

// ---------------- q0 = alpha * I ----------------
__global__ void qinit_kernel(float* __restrict__ q, const float* __restrict__ dmax)
{
    long idx = (long)blockIdx.x * 256 + threadIdx.x;
    int r = (int)((idx >> 8) & 255), c = (int)(idx & 255);
    q[idx] = (r == c) ? (1.0f / dmax[0]) : 0.f;
}

// ---------------- flash attention v2: 128q x 128k tiles, f32x2 ----------------
#define FLASH2_SMEM ((2*64*132 + 128*68 + 128*132) * 4)
__global__ __launch_bounds__(256) void flash2_kernel(
    const float* __restrict__ qmat, const float* __restrict__ kv, float* __restrict__ Y)
{
    int bh = blockIdx.y; int b = bh >> 3, h = bh & 7;
    const float* qb = qmat + (long)b * NQv * INNER + h * DHv;
    const float* kb = kv + (long)b * NN_ * 1024 + h * DHv;
    const float* vb = kb + 512;
    int i0 = blockIdx.x * 128;

    extern __shared__ float sm[];
    float (*Qts)[132] = (float(*)[132])sm;
    float (*Kts)[132] = (float(*)[132])(sm + 64 * 132);
    float (*Vs)[68]   = (float(*)[68]) (sm + 2 * 64 * 132);
    float (*Ps)[132]  = (float(*)[132])(sm + 2 * 64 * 132 + 128 * 68);

    int tid = threadIdx.x, ty = tid >> 4, tx = tid & 15;

    for (int t = tid; t < 128 * 64; t += 256) {
        int r = t >> 6, dd = t & 63;
        Qts[dd][r] = qb[(long)(i0 + r) * INNER + dd];
    }

    float m[8], l[8];
    u64 o2[8][2];         // 8 rows x 2 col-pairs (cols tx*4 .. tx*4+3)
    #pragma unroll
    for (int i = 0; i < 8; i++) {
        m[i] = -1e30f; l[i] = 0.f;
        o2[i][0] = 0ull; o2[i][1] = 0ull;
    }

    for (int c0 = 0; c0 < NN_; c0 += 128) {
        for (int t = tid; t < 128 * 64; t += 256) {
            int r = t >> 6, dd = t & 63;
            Kts[dd][r] = kb[(long)(c0 + r) * 1024 + dd];
            Vs[r][dd]  = vb[(long)(c0 + r) * 1024 + dd];
        }
        __syncthreads();

        // S = Q^T K : i-pairs x 8 cols, f32x2
        u64 s2[4][8] = {};
        #pragma unroll
        for (int d = 0; d < 64; d++) {
            ulonglong2 a01 = *(const ulonglong2*)&Qts[d][ty * 8];
            ulonglong2 a23 = *(const ulonglong2*)&Qts[d][ty * 8 + 4];
            float4 b0 = *(const float4*)&Kts[d][tx * 8];
            float4 b1 = *(const float4*)&Kts[d][tx * 8 + 4];
            u64 ap[4] = {a01.x, a01.y, a23.x, a23.y};
            u64 bd[8] = {dup2(b0.x), dup2(b0.y), dup2(b0.z), dup2(b0.w),
                         dup2(b1.x), dup2(b1.y), dup2(b1.z), dup2(b1.w)};
            #pragma unroll
            for (int p = 0; p < 4; p++)
                #pragma unroll
                for (int j = 0; j < 8; j++)
                    ffma2(s2[p][j], ap[p], bd[j]);
        }

        float s[8][8];
        #pragma unroll
        for (int p = 0; p < 4; p++)
            #pragma unroll
            for (int j = 0; j < 8; j++) {
                float2 f = unpack2(s2[p][j]);
                s[2 * p][j] = f.x;
                s[2 * p + 1][j] = f.y;
            }

        #pragma unroll
        for (int i = 0; i < 8; i++) {
            float rm = s[i][0];
            #pragma unroll
            for (int j = 1; j < 8; j++) rm = fmaxf(rm, s[i][j]);
            #pragma unroll
            for (int off = 8; off > 0; off >>= 1) rm = fmaxf(rm, __shfl_xor_sync(0xffffffffu, rm, off));
            float mn = fmaxf(m[i], rm);
            float corr = __expf(m[i] - mn);
            float rs = 0.f;
            #pragma unroll
            for (int j = 0; j < 8; j++) { s[i][j] = __expf(s[i][j] - mn); rs += s[i][j]; }
            #pragma unroll
            for (int off = 8; off > 0; off >>= 1) rs += __shfl_xor_sync(0xffffffffu, rs, off);
            l[i] = l[i] * corr + rs;
            u64 cd = dup2(corr);
            fmul2(o2[i][0], cd);
            fmul2(o2[i][1], cd);
            m[i] = mn;
            *(float4*)&Ps[ty * 8 + i][tx * 8]     = make_float4(s[i][0], s[i][1], s[i][2], s[i][3]);
            *(float4*)&Ps[ty * 8 + i][tx * 8 + 4] = make_float4(s[i][4], s[i][5], s[i][6], s[i][7]);
        }
        __syncthreads();

        // O += P V : f32x2, col-pairs from V rows
        #pragma unroll 4
        for (int c = 0; c < 128; c += 4) {
            ulonglong2 v0 = *(const ulonglong2*)&Vs[c + 0][tx * 4];
            ulonglong2 v1 = *(const ulonglong2*)&Vs[c + 1][tx * 4];
            ulonglong2 v2 = *(const ulonglong2*)&Vs[c + 2][tx * 4];
            ulonglong2 v3 = *(const ulonglong2*)&Vs[c + 3][tx * 4];
            #pragma unroll
            for (int i = 0; i < 8; i++) {
                float4 p = *(const float4*)&Ps[ty * 8 + i][c];
                u64 pd;
                pd = dup2(p.x); ffma2(o2[i][0], pd, v0.x); ffma2(o2[i][1], pd, v0.y);
                pd = dup2(p.y); ffma2(o2[i][0], pd, v1.x); ffma2(o2[i][1], pd, v1.y);
                pd = dup2(p.z); ffma2(o2[i][0], pd, v2.x); ffma2(o2[i][1], pd, v2.y);
                pd = dup2(p.w); ffma2(o2[i][0], pd, v3.x); ffma2(o2[i][1], pd, v3.y);
            }
        }
        __syncthreads();
    }

    #pragma unroll
    for (int i = 0; i < 8; i++) {
        float inv = 1.f / l[i];
        float2 f0 = unpack2(o2[i][0]);
        float2 f1 = unpack2(o2[i][1]);
        float4 v = make_float4(f0.x * inv, f0.y * inv, f1.x * inv, f1.y * inv);
        *(float4*)&Y[((long)bh * NQv + (i0 + ty * 8 + i)) * DHv + tx * 4] = v;
    }
}

// ---------------- host launch ----------------
static void* sym(const void* s) { void* p = nullptr; cudaGetSymbolAddress(&p, s); return p; }

extern "C" void kernel_launch(void* const* d_in, const int* in_sizes, int n_in,
                              void* d_out, int out_size)
{
    const float* x      = (const float*)d_in[0];
    const float* qin    = (const float*)d_in[1];
    const float* W_kv   = (const float*)d_in[2];
    const float* W_q    = (const float*)d_in[3];
    const float* W_out  = (const float*)d_in[4];
    const float* b_out  = (const float*)d_in[5];
    float* out = (float*)d_out;

    float* kv    = (float*)sym(g_kv);
    float* qmat  = (float*)sym(g_qmat);
    float* kl    = (float*)sym(g_kl);
    float* attn1 = (float*)sym(g_attn1);
    float* G     = (float*)sym(g_G);
    float* qA    = (float*)sym(g_qA);
    float* qB    = (float*)sym(g_qB);
    float* Mb    = (float*)sym(g_M);
    float* r1    = (float*)sym(g_r1);
    float* r2    = (float*)sym(g_r2);
    float* Yb    = (float*)sym(g_Y);
    float* xty   = (float*)sym(g_xty);
    float* z2    = (float*)sym(g_z2);
    float* oc    = (float*)sym(g_oc);
    float* dmax  = (float*)sym(g_max);

    static bool init_done = false;
    static cudaStream_t s1;
    static cudaEvent_t eIn, eKV, eQ, eAttn, eY;
    if (!init_done) {
        cudaFuncSetAttribute(flash2_kernel, cudaFuncAttributeMaxDynamicSharedMemorySize, FLASH2_SMEM);
        cudaStreamCreateWithFlags(&s1, cudaStreamNonBlocking);
        cudaEventCreateWithFlags(&eIn,   cudaEventDisableTiming);
        cudaEventCreateWithFlags(&eKV,   cudaEventDisableTiming);
        cudaEventCreateWithFlags(&eQ,    cudaEventDisableTiming);
        cudaEventCreateWithFlags(&eAttn, cudaEventDisableTiming);
        cudaEventCreateWithFlags(&eY,    cudaEventDisableTiming);
        init_done = true;
    }

    const float scale = 0.125f;
    const long PQ = (long)LMv * LMv;
    const long A1 = (long)NQv * LMv;
    const long YS = (long)NQv * DHv;
    const long XS = (long)LMv * DHv;

    // fork point
    cudaEventRecord(eIn, 0);
    cudaStreamWaitEvent(s1, eIn, 0);

    // s0: kv = x @ W_kv
    sgemm128_kernel<<<dim3(1024/128, 8192/128, 1), 256, 0, 0>>>(
        x, W_kv, nullptr, kv, 8192, 1024, 512, 1.f);

    // s1: qmat = scale * (q_input @ W_q)
    sgemm128_kernel<<<dim3(512/128, 2048/128, 1), 256, 0, s1>>>(
        qin, W_q, nullptr, qmat, 2048, 512, 512, scale);
    cudaEventRecord(eQ, s1);

    // s0: landmarks
    landmark_kernel<<<dim3(256, 16), 64, 0, 0>>>(kv, kl);
    cudaEventRecord(eKV, 0);

    // s0: sim1 = q @ kl^T
    cudaStreamWaitEvent(0, eQ, 0);
    sgemm_kernel<<<dim3(256/64, 1024/64, 16), 256, 0, 0>>>(
        qmat, kl, nullptr, nullptr, attn1, 1024, 256, 64,
        (long)NQv*INNER, 64,  8*XS, XS,  0,0,  8*A1, A1,
        512,1, 1,64, 256, 1.f, 0.f);

    // s0: softmax
    softmax256_kernel<<<(BHv * NQv) / 8, 256, 0, 0>>>(attn1);
    cudaEventRecord(eAttn, 0);

    // ---- s1 branch: flash, then xty ----
    cudaStreamWaitEvent(s1, eKV, 0);
    flash2_kernel<<<dim3(NQv / 128, 16), 256, FLASH2_SMEM, s1>>>(qmat, kv, Yb);
    cudaStreamWaitEvent(s1, eAttn, 0);
    gemm_tile_kernel<1><<<dim3(1, 2, 16), 256, 0, s1>>>(
        attn1, Yb, nullptr, xty, 1024, 256, 64, 64,
        8*A1, A1, 8*YS, YS, 0,0, 8*XS, XS, 1.f, 0.f);
    cudaEventRecord(eY, s1);

    // ---- s0 branch: G + alpha + pinv chain ----
    gemm_tile_kernel<1><<<dim3(4, 2, 16), 256, 0, 0>>>(
        attn1, attn1, nullptr, G, 1024, 256, 256, 256,
        8*A1, A1, 8*A1, A1, 0,0, 8*PQ, PQ, 1.f, 0.f);

    initmax_kernel<<<1, 1, 0, 0>>>(dmax);
    colsummax_kernel<<<16, 256, 0, 0>>>(attn1, dmax);
    qinit_kernel<<<(BHv * 256 * 256) / 256, 256, 0, 0>>>(qA, dmax);

    float* qc = qA; float* qn = qB;
    for (int it = 0; it < 6; it++) {
        gemm_tile_kernel<0><<<dim3(4, 2, 16), 256, 0, 0>>>(
            qc, G, nullptr, Mb, 256, 256, 256, 256,
            8*PQ, PQ, 8*PQ, PQ, 0,0, 8*PQ, PQ, 1.f, 0.f);
        gemm_tile_kernel<0><<<dim3(4, 2, 16), 256, 0, 0>>>(
            Mb, qc, qc, r1, 256, 256, 256, 256,
            8*PQ, PQ, 8*PQ, PQ, 8*PQ, PQ, 8*PQ, PQ, -1.f, 7.f);
        gemm_tile_kernel<0><<<dim3(4, 2, 16), 256, 0, 0>>>(
            Mb, r1, qc, r2, 256, 256, 256, 256,
            8*PQ, PQ, 8*PQ, PQ, 8*PQ, PQ, 8*PQ, PQ, -1.f, 15.f);
        gemm_tile_kernel<0><<<dim3(4, 2, 16), 256, 0, 0>>>(
            Mb, r2, qc, qn, 256, 256, 256, 256,
            8*PQ, PQ, 8*PQ, PQ, 8*PQ, PQ, 8*PQ, PQ, -0.25f, 3.25f);
        float* t = qc; qc = qn; qn = t;
    }

    // join
    cudaStreamWaitEvent(0, eY, 0);

    gemm_tile_kernel<0><<<dim3(1, 2, 16), 256, 0, 0>>>(
        qc, xty, nullptr, z2, 256, 256, 64, 64,
        8*PQ, PQ, 8*XS, XS, 0,0, 8*XS, XS, 1.f, 0.f);

    gemm_tile_kernel<0><<<dim3(1, 8, 16), 256, 0, 0>>>(
        attn1, z2, nullptr, oc, 256, 256, 64, 512,
        8*A1, A1, 8*XS, XS, 0,0, (long)NQv*INNER, 64, 1.f, 0.f);

    sgemm128_kernel<<<dim3(512/128, 2048/128, 1), 256, 0, 0>>>(
        oc, W_out, b_out, out, 2048, 512, 512, 1.f);
}

// round 8
// speedup vs baseline: 1.0744x; 1.0009x over previous
#include <cuda_runtime.h>
#include <cuda_bf16.h>

// Problem constants
#define BB   2
#define NN_  4096
#define NQv  1024
#define DIMv 512
#define HH   8
#define DHv  64
#define LMv  256
#define BHv  16
#define INNER 512

typedef unsigned long long u64;

// ---------------- f32x2 packed helpers (Blackwell) ----------------
__device__ __forceinline__ void ffma2(u64 &d, u64 a, u64 b) {
    asm("fma.rn.f32x2 %0, %1, %2, %0;" : "+l"(d) : "l"(a), "l"(b));
}
__device__ __forceinline__ u64 pack2(float x, float y) {
    u64 r; asm("mov.b64 %0, {%1, %2};" : "=l"(r) : "f"(x), "f"(y)); return r;
}
__device__ __forceinline__ u64 dup2(float x) { return pack2(x, x); }
__device__ __forceinline__ float2 unpack2(u64 v) {
    float lo, hi; asm("mov.b64 {%0, %1}, %2;" : "=f"(lo), "=f"(hi) : "l"(v));
    return make_float2(lo, hi);
}
__device__ __forceinline__ void fmul2(u64 &d, u64 a) {
    asm("mul.rn.f32x2 %0, %0, %1;" : "+l"(d) : "l"(a));
}

// ---------------- scratch (device globals; no allocation allowed) ----------------
__device__ float g_kv[(long)BB*NN_*1024];
__device__ float g_qmat[(long)BB*NQv*INNER];
__device__ float g_klT[BHv*DHv*LMv];           // landmarks TRANSPOSED (bh, 64, 256)
__device__ float g_attn1[(long)BHv*NQv*LMv];
__device__ float g_G[BHv*LMv*LMv];
__device__ float g_qA[BHv*LMv*LMv];
__device__ float g_qB[BHv*LMv*LMv];
__device__ float g_M[BHv*LMv*LMv];
__device__ float g_r1[BHv*LMv*LMv];
__device__ float g_r2[BHv*LMv*LMv];
__device__ float g_Y[BHv*NQv*DHv];
__device__ float g_xty[BHv*LMv*DHv];
__device__ float g_z2[BHv*LMv*DHv];
__device__ float g_oc[(long)BB*NQv*INNER];
__device__ float g_max[1];

// ---------------- 128x128 SGEMM, f32x2 accumulators ----------------
__global__ __launch_bounds__(256) void sgemm128_kernel(
    const float* __restrict__ A, const float* __restrict__ B,
    const float* __restrict__ bias, float* __restrict__ C,
    int M, int N, int K, float alpha)
{
    __shared__ float As[2][8][132];
    __shared__ float Bs[2][8][128];

    int tid = threadIdx.x;
    int ty = tid >> 4, tx = tid & 15;
    int i0 = blockIdx.y * 128, j0 = blockIdx.x * 128;

    int arow = tid >> 1, akq = (tid & 1) * 4;
    int bkr = tid >> 5, bcq = (tid & 31) * 4;

    const float* Aptr = A + (long)(i0 + arow) * K + akq;
    const float* Bptr = B + (long)bkr * N + j0 + bcq;

    float4 av = *(const float4*)Aptr;
    float4 bv = *(const float4*)Bptr;
    As[0][akq + 0][arow] = av.x; As[0][akq + 1][arow] = av.y;
    As[0][akq + 2][arow] = av.z; As[0][akq + 3][arow] = av.w;
    *(float4*)&Bs[0][bkr][bcq] = bv;
    __syncthreads();

    u64 acc2[4][8] = {};
    int T = K / 8;
    int buf = 0;
    for (int t = 0; t < T; t++) {
        if (t + 1 < T) {
            av = *(const float4*)(Aptr + (t + 1) * 8);
            bv = *(const float4*)(Bptr + (long)(t + 1) * 8 * N);
        }
        #pragma unroll
        for (int kk = 0; kk < 8; kk++) {
            ulonglong2 a01 = *(const ulonglong2*)&As[buf][kk][ty * 8];
            ulonglong2 a23 = *(const ulonglong2*)&As[buf][kk][ty * 8 + 4];
            float4 b0 = *(const float4*)&Bs[buf][kk][tx * 8];
            float4 b1 = *(const float4*)&Bs[buf][kk][tx * 8 + 4];
            u64 ap[4] = {a01.x, a01.y, a23.x, a23.y};
            u64 bd[8] = {dup2(b0.x), dup2(b0.y), dup2(b0.z), dup2(b0.w),
                         dup2(b1.x), dup2(b1.y), dup2(b1.z), dup2(b1.w)};
            #pragma unroll
            for (int p = 0; p < 4; p++)
                #pragma unroll
                for (int j = 0; j < 8; j++)
                    ffma2(acc2[p][j], ap[p], bd[j]);
        }
        if (t + 1 < T) {
            int nb = buf ^ 1;
            As[nb][akq + 0][arow] = av.x; As[nb][akq + 1][arow] = av.y;
            As[nb][akq + 2][arow] = av.z; As[nb][akq + 3][arow] = av.w;
            *(float4*)&Bs[nb][bkr][bcq] = bv;
            __syncthreads();
            buf = nb;
        }
    }

    #pragma unroll
    for (int p = 0; p < 4; p++) {
        float2 c[8];
        #pragma unroll
        for (int j = 0; j < 8; j++) c[j] = unpack2(acc2[p][j]);
        #pragma unroll
        for (int half = 0; half < 2; half++) {
            long row = i0 + ty * 8 + 2 * p + half;
            #pragma unroll
            for (int jq = 0; jq < 2; jq++) {
                int col = j0 + tx * 8 + jq * 4;
                float4 v;
                v.x = alpha * (half ? c[jq*4+0].y : c[jq*4+0].x);
                v.y = alpha * (half ? c[jq*4+1].y : c[jq*4+1].x);
                v.z = alpha * (half ? c[jq*4+2].y : c[jq*4+2].x);
                v.w = alpha * (half ? c[jq*4+3].y : c[jq*4+3].x);
                if (bias) {
                    v.x += bias[col + 0]; v.y += bias[col + 1];
                    v.z += bias[col + 2]; v.w += bias[col + 3];
                }
                *(float4*)&C[row * N + col] = v;
            }
        }
    }
}

// ---------------- batched 128x64-tile GEMM, f32x2, double buffered ----------------
template<int TRANSA>
__global__ __launch_bounds__(256) void gemm_tile_kernel(
    const float* __restrict__ A, const float* __restrict__ B,
    const float* __restrict__ D, float* __restrict__ C,
    int K, int lda, int ldb, int ldc,
    long sAo, long sAi, long sBo, long sBi, long sDo, long sDi, long sCo, long sCi,
    float alpha, float beta)
{
    int z = blockIdx.z; int zb = z >> 3, zh = z & 7;
    A += zb * sAo + zh * sAi;
    B += zb * sBo + zh * sBi;
    C += zb * sCo + zh * sCi;
    if (D) D += zb * sDo + zh * sDi;

    __shared__ float As[2][8][132];
    __shared__ float Bs[2][8][68];

    int tid = threadIdx.x;
    int ty = tid >> 4, tx = tid & 15;
    int i0 = blockIdx.y * 128, j0 = blockIdx.x * 64;

    int a_kr = tid >> 5;
    int a_iq = (tid & 31) * 4;
    int a_row = tid >> 1;
    int a_kq = (tid & 1) * 4;
    int b_kr = tid >> 4;
    int b_cq = (tid & 15) * 4;

    const float* Aptr = TRANSA ? (A + (long)a_kr * lda + i0 + a_iq)
                               : (A + (long)(i0 + a_row) * lda + a_kq);
    const float* Bptr = B + (long)b_kr * ldb + j0 + b_cq;

    float4 av = *(const float4*)Aptr;
    float4 bv = make_float4(0.f, 0.f, 0.f, 0.f);
    if (tid < 128) bv = *(const float4*)Bptr;

    if (TRANSA) {
        *(float4*)&As[0][a_kr][a_iq] = av;
    } else {
        As[0][a_kq + 0][a_row] = av.x; As[0][a_kq + 1][a_row] = av.y;
        As[0][a_kq + 2][a_row] = av.z; As[0][a_kq + 3][a_row] = av.w;
    }
    if (tid < 128) *(float4*)&Bs[0][b_kr][b_cq] = bv;
    __syncthreads();

    u64 acc2[4][4] = {};
    int T = K / 8;
    int buf = 0;
    for (int t = 0; t < T; t++) {
        if (t + 1 < T) {
            av = TRANSA ? *(const float4*)(Aptr + (long)(t + 1) * 8 * lda)
                        : *(const float4*)(Aptr + (t + 1) * 8);
            if (tid < 128) bv = *(const float4*)(Bptr + (long)(t + 1) * 8 * ldb);
        }
        #pragma unroll
        for (int kk = 0; kk < 8; kk++) {
            ulonglong2 a01 = *(const ulonglong2*)&As[buf][kk][ty * 8];
            ulonglong2 a23 = *(const ulonglong2*)&As[buf][kk][ty * 8 + 4];
            float4 b0 = *(const float4*)&Bs[buf][kk][tx * 4];
            u64 ap[4] = {a01.x, a01.y, a23.x, a23.y};
            u64 bd[4] = {dup2(b0.x), dup2(b0.y), dup2(b0.z), dup2(b0.w)};
            #pragma unroll
            for (int p = 0; p < 4; p++) {
                ffma2(acc2[p][0], ap[p], bd[0]);
                ffma2(acc2[p][1], ap[p], bd[1]);
                ffma2(acc2[p][2], ap[p], bd[2]);
                ffma2(acc2[p][3], ap[p], bd[3]);
            }
        }
        if (t + 1 < T) {
            int nb = buf ^ 1;
            if (TRANSA) {
                *(float4*)&As[nb][a_kr][a_iq] = av;
            } else {
                As[nb][a_kq + 0][a_row] = av.x; As[nb][a_kq + 1][a_row] = av.y;
                As[nb][a_kq + 2][a_row] = av.z; As[nb][a_kq + 3][a_row] = av.w;
            }
            if (tid < 128) *(float4*)&Bs[nb][b_kr][b_cq] = bv;
            __syncthreads();
            buf = nb;
        }
    }

    #pragma unroll
    for (int p = 0; p < 4; p++) {
        float2 c0 = unpack2(acc2[p][0]);
        float2 c1 = unpack2(acc2[p][1]);
        float2 c2 = unpack2(acc2[p][2]);
        float2 c3 = unpack2(acc2[p][3]);
        #pragma unroll
        for (int half = 0; half < 2; half++) {
            long row = i0 + ty * 8 + 2 * p + half;
            long off = row * ldc + j0 + tx * 4;
            float4 v;
            v.x = alpha * (half ? c0.y : c0.x);
            v.y = alpha * (half ? c1.y : c1.x);
            v.z = alpha * (half ? c2.y : c2.x);
            v.w = alpha * (half ? c3.y : c3.x);
            if (D) {
                float4 dv = *(const float4*)&D[off];
                v.x += beta * dv.x; v.y += beta * dv.y;
                v.z += beta * dv.z; v.w += beta * dv.w;
            }
            *(float4*)&C[off] = v;
        }
    }
}

// ---------------- landmark pooling (writes TRANSPOSED klT[bh][d][m]) ----------------
__global__ void landmark_kernel(const float* __restrict__ kv, float* __restrict__ klT)
{
    int dd = threadIdx.x;
    int j  = blockIdx.x;
    int bh = blockIdx.y;
    int b = bh >> 3, h = bh & 7;
    const float* base = kv + (long)b * NN_ * 1024 + (long)(j * 16) * 1024 + h * DHv + dd;
    float s = 0.f;
    #pragma unroll
    for (int t = 0; t < 16; t++) s += base[(long)t * 1024];
    klT[((long)bh * DHv + dd) * LMv + j] = s;
}

// ---------------- row softmax over 256 columns (in place) ----------------
__global__ void softmax256_kernel(float* __restrict__ a)
{
    int row = blockIdx.x * 8 + (threadIdx.x >> 5);
    int lane = threadIdx.x & 31;
    float* p = a + (long)row * 256;
    float v[8];
    float mx = -1e30f;
    #pragma unroll
    for (int t = 0; t < 8; t++) { v[t] = p[lane + 32 * t]; mx = fmaxf(mx, v[t]); }
    #pragma unroll
    for (int o = 16; o > 0; o >>= 1) mx = fmaxf(mx, __shfl_xor_sync(0xffffffffu, mx, o));
    float s = 0.f;
    #pragma unroll
    for (int t = 0; t < 8; t++) { v[t] = __expf(v[t] - mx); s += v[t]; }
    #pragma unroll
    for (int o = 16; o > 0; o >>= 1) s += __shfl_xor_sync(0xffffffffu, s, o);
    float inv = 1.f / s;
    #pragma unroll
    for (int t = 0; t < 8; t++) p[lane + 32 * t] = v[t] * inv;
}

// ---------------- column sums of attn1 + global max ----------------
__global__ void initmax_kernel(float* m) { m[0] = 0.f; }

__global__ void colsummax_kernel(const float* __restrict__ a, float* __restrict__ dmax)
{
    int idx = blockIdx.x * blockDim.x + threadIdx.x;
    int bh = idx >> 8, j = idx & 255;
    const float* p = a + (long)bh * NQv * LMv + j;
    float s = 0.f;
    for (int i = 0; i < NQv; i++) s += p[(long)i * 256];
    atomicMax((int*)dmax, __float_as_int(s));
}

// ---------------- q0 = alpha * I ----------------
__global__ void qinit_kernel(float* __restrict__ q, const float* __restrict__ dmax)
{
    long idx = (long)blockIdx.x * 256 + threadIdx.x;
    int r = (int)((idx >> 8) & 255), c = (int)(idx & 255);
    q[idx] = (r == c) ? (1.0f / dmax[0]) : 0.f;
}

// ---------------- flash attention v3: 128q x 128k tiles, f32x2, low reg pressure ----
#define FLASH2_SMEM ((2*64*132 + 128*68 + 128*132) * 4)
__global__ __launch_bounds__(256) void flash2_kernel(
    const float* __restrict__ qmat, const float* __restrict__ kv, float* __restrict__ Y)
{
    int bh = blockIdx.y; int b = bh >> 3, h = bh & 7;
    const float* qb = qmat + (long)b * NQv * INNER + h * DHv;
    const float* kb = kv + (long)b * NN_ * 1024 + h * DHv;
    const float* vb = kb + 512;
    int i0 = blockIdx.x * 128;

    extern __shared__ float sm[];
    float (*Qts)[132] = (float(*)[132])sm;
    float (*Kts)[132] = (float(*)[132])(sm + 64 * 132);
    float (*Vs)[68]   = (float(*)[68]) (sm + 2 * 64 * 132);
    float (*Ps)[132]  = (float(*)[132])(sm + 2 * 64 * 132 + 128 * 68);

    int tid = threadIdx.x, ty = tid >> 4, tx = tid & 15;
    int lr = tid >> 4;            // 0..15 (row-within-group for vector loads)
    int ldq = (tid & 15) << 2;    // 0..60 (d quad for vector loads)

    // Q tile load (vectorized LDG, scalar transpose STS)
    #pragma unroll
    for (int u = 0; u < 8; u++) {
        int r = u * 16 + lr;
        float4 f = *(const float4*)(qb + (long)(i0 + r) * INNER + ldq);
        Qts[ldq + 0][r] = f.x; Qts[ldq + 1][r] = f.y;
        Qts[ldq + 2][r] = f.z; Qts[ldq + 3][r] = f.w;
    }

    float m[8], l[8];
    u64 o2[8][2];
    #pragma unroll
    for (int i = 0; i < 8; i++) {
        m[i] = -1e30f; l[i] = 0.f;
        o2[i][0] = 0ull; o2[i][1] = 0ull;
    }

    for (int c0 = 0; c0 < NN_; c0 += 128) {
        // K: scalar coalesced loads + transpose store (4-way STS conflicts, acceptable)
        #pragma unroll
        for (int t = tid; t < 128 * 64; t += 256) {
            int r = t >> 6, dd = t & 63;
            Kts[dd][r] = kb[(long)(c0 + r) * 1024 + dd];
        }
        // V: vectorized LDG + float4 STS (natural layout, conflict-free)
        #pragma unroll
        for (int u = 0; u < 8; u++) {
            int r = u * 16 + lr;
            float4 fv = *(const float4*)(vb + (long)(c0 + r) * 1024 + ldq);
            *(float4*)&Vs[r][ldq] = fv;
        }
        __syncthreads();

        // S = Q^T K : 4 row-pairs x 8 cols, f32x2
        u64 s2[4][8] = {};
        #pragma unroll
        for (int d = 0; d < 64; d++) {
            ulonglong2 a01 = *(const ulonglong2*)&Qts[d][ty * 8];
            ulonglong2 a23 = *(const ulonglong2*)&Qts[d][ty * 8 + 4];
            float4 b0 = *(const float4*)&Kts[d][tx * 8];
            float4 b1 = *(const float4*)&Kts[d][tx * 8 + 4];
            u64 ap[4] = {a01.x, a01.y, a23.x, a23.y};
            u64 bd[8] = {dup2(b0.x), dup2(b0.y), dup2(b0.z), dup2(b0.w),
                         dup2(b1.x), dup2(b1.y), dup2(b1.z), dup2(b1.w)};
            #pragma unroll
            for (int p = 0; p < 4; p++)
                #pragma unroll
                for (int j = 0; j < 8; j++)
                    ffma2(s2[p][j], ap[p], bd[j]);
        }

        // online softmax per row-pair, directly from packed s2 (no 64-reg unpack)
        #pragma unroll
        for (int p = 0; p < 4; p++) {
            int r0 = 2 * p, r1 = 2 * p + 1;
            float mx0 = -1e30f, mx1 = -1e30f;
            #pragma unroll
            for (int j = 0; j < 8; j++) {
                float2 f = unpack2(s2[p][j]);
                mx0 = fmaxf(mx0, f.x); mx1 = fmaxf(mx1, f.y);
            }
            #pragma unroll
            for (int off = 8; off > 0; off >>= 1) {
                mx0 = fmaxf(mx0, __shfl_xor_sync(0xffffffffu, mx0, off));
                mx1 = fmaxf(mx1, __shfl_xor_sync(0xffffffffu, mx1, off));
            }
            float mn0 = fmaxf(m[r0], mx0), mn1 = fmaxf(m[r1], mx1);
            float corr0 = __expf(m[r0] - mn0), corr1 = __expf(m[r1] - mn1);
            float rs0 = 0.f, rs1 = 0.f;
            #pragma unroll
            for (int j = 0; j < 8; j++) {
                float2 f = unpack2(s2[p][j]);
                float e0 = __expf(f.x - mn0);
                float e1 = __expf(f.y - mn1);
                rs0 += e0; rs1 += e1;
                Ps[ty * 8 + r0][tx * 8 + j] = e0;
                Ps[ty * 8 + r1][tx * 8 + j] = e1;
            }
            #pragma unroll
            for (int off = 8; off > 0; off >>= 1) {
                rs0 += __shfl_xor_sync(0xffffffffu, rs0, off);
                rs1 += __shfl_xor_sync(0xffffffffu, rs1, off);
            }
            l[r0] = l[r0] * corr0 + rs0;
            l[r1] = l[r1] * corr1 + rs1;
            u64 cd0 = dup2(corr0), cd1 = dup2(corr1);
            fmul2(o2[r0][0], cd0); fmul2(o2[r0][1], cd0);
            fmul2(o2[r1][0], cd1); fmul2(o2[r1][1], cd1);
            m[r0] = mn0; m[r1] = mn1;
        }
        __syncthreads();

        // O += P V : f32x2
        #pragma unroll 4
        for (int c = 0; c < 128; c += 4) {
            ulonglong2 v0 = *(const ulonglong2*)&Vs[c + 0][tx * 4];
            ulonglong2 v1 = *(const ulonglong2*)&Vs[c + 1][tx * 4];
            ulonglong2 v2 = *(const ulonglong2*)&Vs[c + 2][tx * 4];
            ulonglong2 v3 = *(const ulonglong2*)&Vs[c + 3][tx * 4];
            #pragma unroll
            for (int i = 0; i < 8; i++) {
                float4 p = *(const float4*)&Ps[ty * 8 + i][c];
                u64 pd;
                pd = dup2(p.x); ffma2(o2[i][0], pd, v0.x); ffma2(o2[i][1], pd, v0.y);
                pd = dup2(p.y); ffma2(o2[i][0], pd, v1.x); ffma2(o2[i][1], pd, v1.y);
                pd = dup2(p.z); ffma2(o2[i][0], pd, v2.x); ffma2(o2[i][1], pd, v2.y);
                pd = dup2(p.w); ffma2(o2[i][0], pd, v3.x); ffma2(o2[i][1], pd, v3.y);
            }
        }
        __syncthreads();
    }

    #pragma unroll
    for (int i = 0; i < 8; i++) {
        float inv = 1.f / l[i];
        float2 f0 = unpack2(o2[i][0]);
        float2 f1 = unpack2(o2[i][1]);
        float4 v = make_float4(f0.x * inv, f0.y * inv, f1.x * inv, f1.y * inv);
        *(float4*)&Y[((long)bh * NQv + (i0 + ty * 8 + i)) * DHv + tx * 4] = v;
    }
}

// ---------------- host launch ----------------
static void* sym(const void* s) { void* p = nullptr; cudaGetSymbolAddress(&p, s); return p; }

extern "C" void kernel_launch(void* const* d_in, const int* in_sizes, int n_in,
                              void* d_out, int out_size)
{
    const float* x      = (const float*)d_in[0];
    const float* qin    = (const float*)d_in[1];
    const float* W_kv   = (const float*)d_in[2];
    const float* W_q    = (const float*)d_in[3];
    const float* W_out  = (const float*)d_in[4];
    const float* b_out  = (const float*)d_in[5];
    float* out = (float*)d_out;

    float* kv    = (float*)sym(g_kv);
    float* qmat  = (float*)sym(g_qmat);
    float* klT   = (float*)sym(g_klT);
    float* attn1 = (float*)sym(g_attn1);
    float* G     = (float*)sym(g_G);
    float* qA    = (float*)sym(g_qA);
    float* qB    = (float*)sym(g_qB);
    float* Mb    = (float*)sym(g_M);
    float* r1    = (float*)sym(g_r1);
    float* r2    = (float*)sym(g_r2);
    float* Yb    = (float*)sym(g_Y);
    float* xty   = (float*)sym(g_xty);
    float* z2    = (float*)sym(g_z2);
    float* oc    = (float*)sym(g_oc);
    float* dmax  = (float*)sym(g_max);

    static bool init_done = false;
    static cudaStream_t s1;
    static cudaEvent_t eIn, eKV, eQ, eAttn, eY;
    if (!init_done) {
        cudaFuncSetAttribute(flash2_kernel, cudaFuncAttributeMaxDynamicSharedMemorySize, FLASH2_SMEM);
        cudaStreamCreateWithFlags(&s1, cudaStreamNonBlocking);
        cudaEventCreateWithFlags(&eIn,   cudaEventDisableTiming);
        cudaEventCreateWithFlags(&eKV,   cudaEventDisableTiming);
        cudaEventCreateWithFlags(&eQ,    cudaEventDisableTiming);
        cudaEventCreateWithFlags(&eAttn, cudaEventDisableTiming);
        cudaEventCreateWithFlags(&eY,    cudaEventDisableTiming);
        init_done = true;
    }

    const float scale = 0.125f;
    const long PQ = (long)LMv * LMv;
    const long A1 = (long)NQv * LMv;
    const long YS = (long)NQv * DHv;
    const long XS = (long)LMv * DHv;

    // fork point
    cudaEventRecord(eIn, 0);
    cudaStreamWaitEvent(s1, eIn, 0);

    // launch #1  s0: kv = x @ W_kv
    sgemm128_kernel<<<dim3(1024/128, 8192/128, 1), 256, 0, 0>>>(
        x, W_kv, nullptr, kv, 8192, 1024, 512, 1.f);
    cudaEventRecord(eKV, 0);      // kv ready (flash needs only kv, not landmarks)

    // launch #2  s1: qmat = scale * (q_input @ W_q)
    sgemm128_kernel<<<dim3(512/128, 2048/128, 1), 256, 0, s1>>>(
        qin, W_q, nullptr, qmat, 2048, 512, 512, scale);
    cudaEventRecord(eQ, s1);

    // launch #3  s0: landmarks (transposed output)
    landmark_kernel<<<dim3(256, 16), 64, 0, 0>>>(kv, klT);

    // launch #4  s1: flash (after qmat on s1; waits kv) — positioned for ncu profiling
    cudaStreamWaitEvent(s1, eKV, 0);
    flash2_kernel<<<dim3(NQv / 128, 16), 256, FLASH2_SMEM, s1>>>(qmat, kv, Yb);

    // launch #5  s0: sim1 = q @ klT  (needs qmat + landmarks)
    cudaStreamWaitEvent(0, eQ, 0);
    gemm_tile_kernel<0><<<dim3(4, 8, 16), 256, 0, 0>>>(
        qmat, klT, nullptr, attn1, 64, 512, 256, 256,
        (long)NQv*INNER, 64, 8*(long)DHv*LMv, (long)DHv*LMv, 0,0, 8*A1, A1, 1.f, 0.f);

    // launch #6  s0: softmax
    softmax256_kernel<<<(BHv * NQv) / 8, 256, 0, 0>>>(attn1);
    cudaEventRecord(eAttn, 0);

    // s1: xty = attn1^T @ Y (after flash; waits attn1)
    cudaStreamWaitEvent(s1, eAttn, 0);
    gemm_tile_kernel<1><<<dim3(1, 2, 16), 256, 0, s1>>>(
        attn1, Yb, nullptr, xty, 1024, 256, 64, 64,
        8*A1, A1, 8*YS, YS, 0,0, 8*XS, XS, 1.f, 0.f);
    cudaEventRecord(eY, s1);

    // ---- s0 branch: G + alpha + pinv chain ----
    gemm_tile_kernel<1><<<dim3(4, 2, 16), 256, 0, 0>>>(
        attn1, attn1, nullptr, G, 1024, 256, 256, 256,
        8*A1, A1, 8*A1, A1, 0,0, 8*PQ, PQ, 1.f, 0.f);

    initmax_kernel<<<1, 1, 0, 0>>>(dmax);
    colsummax_kernel<<<16, 256, 0, 0>>>(attn1, dmax);
    qinit_kernel<<<(BHv * 256 * 256) / 256, 256, 0, 0>>>(qA, dmax);

    float* qc = qA; float* qn = qB;
    for (int it = 0; it < 6; it++) {
        gemm_tile_kernel<0><<<dim3(4, 2, 16), 256, 0, 0>>>(
            qc, G, nullptr, Mb, 256, 256, 256, 256,
            8*PQ, PQ, 8*PQ, PQ, 0,0, 8*PQ, PQ, 1.f, 0.f);
        gemm_tile_kernel<0><<<dim3(4, 2, 16), 256, 0, 0>>>(
            Mb, qc, qc, r1, 256, 256, 256, 256,
            8*PQ, PQ, 8*PQ, PQ, 8*PQ, PQ, 8*PQ, PQ, -1.f, 7.f);
        gemm_tile_kernel<0><<<dim3(4, 2, 16), 256, 0, 0>>>(
            Mb, r1, qc, r2, 256, 256, 256, 256,
            8*PQ, PQ, 8*PQ, PQ, 8*PQ, PQ, 8*PQ, PQ, -1.f, 15.f);
        gemm_tile_kernel<0><<<dim3(4, 2, 16), 256, 0, 0>>>(
            Mb, r2, qc, qn, 256, 256, 256, 256,
            8*PQ, PQ, 8*PQ, PQ, 8*PQ, PQ, 8*PQ, PQ, -0.25f, 3.25f);
        float* t = qc; qc = qn; qn = t;
    }

    // join
    cudaStreamWaitEvent(0, eY, 0);

    gemm_tile_kernel<0><<<dim3(1, 2, 16), 256, 0, 0>>>(
        qc, xty, nullptr, z2, 256, 256, 64, 64,
        8*PQ, PQ, 8*XS, XS, 0,0, 8*XS, XS, 1.f, 0.f);

    gemm_tile_kernel<0><<<dim3(1, 8, 16), 256, 0, 0>>>(
        attn1, z2, nullptr, oc, 256, 256, 64, 512,
        8*A1, A1, 8*XS, XS, 0,0, (long)NQv*INNER, 64, 1.f, 0.f);

    sgemm128_kernel<<<dim3(512/128, 2048/128, 1), 256, 0, 0>>>(
        oc, W_out, b_out, out, 2048, 512, 512, 1.f);
}

// round 9
// speedup vs baseline: 1.0992x; 1.0231x over previous
#include <cuda_runtime.h>
#include <cuda_bf16.h>

// Problem constants
#define BB   2
#define NN_  4096
#define NQv  1024
#define DIMv 512
#define HH   8
#define DHv  64
#define LMv  256
#define BHv  16
#define INNER 512

typedef unsigned long long u64;

// ---------------- f32x2 packed helpers (Blackwell) ----------------
__device__ __forceinline__ void ffma2(u64 &d, u64 a, u64 b) {
    asm("fma.rn.f32x2 %0, %1, %2, %0;" : "+l"(d) : "l"(a), "l"(b));
}
__device__ __forceinline__ u64 pack2(float x, float y) {
    u64 r; asm("mov.b64 %0, {%1, %2};" : "=l"(r) : "f"(x), "f"(y)); return r;
}
__device__ __forceinline__ u64 dup2(float x) { return pack2(x, x); }
__device__ __forceinline__ float2 unpack2(u64 v) {
    float lo, hi; asm("mov.b64 {%0, %1}, %2;" : "=f"(lo), "=f"(hi) : "l"(v));
    return make_float2(lo, hi);
}
__device__ __forceinline__ void fmul2(u64 &d, u64 a) {
    asm("mul.rn.f32x2 %0, %0, %1;" : "+l"(d) : "l"(a));
}

// ---------------- scratch (device globals; no allocation allowed) ----------------
__device__ float g_kv[(long)BB*NN_*1024];
__device__ float g_qmat[(long)BB*NQv*INNER];
__device__ float g_klT[BHv*DHv*LMv];           // landmarks TRANSPOSED (bh, 64, 256)
__device__ float g_attn1[(long)BHv*NQv*LMv];
__device__ float g_G[BHv*LMv*LMv];
__device__ float g_qA[BHv*LMv*LMv];
__device__ float g_qB[BHv*LMv*LMv];
__device__ float g_M[BHv*LMv*LMv];
__device__ float g_r1[BHv*LMv*LMv];
__device__ float g_r2[BHv*LMv*LMv];
__device__ float g_Y[BHv*NQv*DHv];
__device__ float g_xty[BHv*LMv*DHv];
__device__ float g_z2[BHv*LMv*DHv];
__device__ float g_oc[(long)BB*NQv*INNER];
__device__ float g_max[1];

// ---------------- 128x128 SGEMM, f32x2 accumulators (big contiguous GEMMs) -------
__global__ __launch_bounds__(256) void sgemm128_kernel(
    const float* __restrict__ A, const float* __restrict__ B,
    const float* __restrict__ bias, float* __restrict__ C,
    int M, int N, int K, float alpha)
{
    __shared__ float As[2][8][132];
    __shared__ float Bs[2][8][128];

    int tid = threadIdx.x;
    int ty = tid >> 4, tx = tid & 15;
    int i0 = blockIdx.y * 128, j0 = blockIdx.x * 128;

    int arow = tid >> 1, akq = (tid & 1) * 4;
    int bkr = tid >> 5, bcq = (tid & 31) * 4;

    const float* Aptr = A + (long)(i0 + arow) * K + akq;
    const float* Bptr = B + (long)bkr * N + j0 + bcq;

    float4 av = *(const float4*)Aptr;
    float4 bv = *(const float4*)Bptr;
    As[0][akq + 0][arow] = av.x; As[0][akq + 1][arow] = av.y;
    As[0][akq + 2][arow] = av.z; As[0][akq + 3][arow] = av.w;
    *(float4*)&Bs[0][bkr][bcq] = bv;
    __syncthreads();

    u64 acc2[4][8] = {};
    int T = K / 8;
    int buf = 0;
    for (int t = 0; t < T; t++) {
        if (t + 1 < T) {
            av = *(const float4*)(Aptr + (t + 1) * 8);
            bv = *(const float4*)(Bptr + (long)(t + 1) * 8 * N);
        }
        #pragma unroll
        for (int kk = 0; kk < 8; kk++) {
            ulonglong2 a01 = *(const ulonglong2*)&As[buf][kk][ty * 8];
            ulonglong2 a23 = *(const ulonglong2*)&As[buf][kk][ty * 8 + 4];
            float4 b0 = *(const float4*)&Bs[buf][kk][tx * 8];
            float4 b1 = *(const float4*)&Bs[buf][kk][tx * 8 + 4];
            u64 ap[4] = {a01.x, a01.y, a23.x, a23.y};
            u64 bd[8] = {dup2(b0.x), dup2(b0.y), dup2(b0.z), dup2(b0.w),
                         dup2(b1.x), dup2(b1.y), dup2(b1.z), dup2(b1.w)};
            #pragma unroll
            for (int p = 0; p < 4; p++)
                #pragma unroll
                for (int j = 0; j < 8; j++)
                    ffma2(acc2[p][j], ap[p], bd[j]);
        }
        if (t + 1 < T) {
            int nb = buf ^ 1;
            As[nb][akq + 0][arow] = av.x; As[nb][akq + 1][arow] = av.y;
            As[nb][akq + 2][arow] = av.z; As[nb][akq + 3][arow] = av.w;
            *(float4*)&Bs[nb][bkr][bcq] = bv;
            __syncthreads();
            buf = nb;
        }
    }

    #pragma unroll
    for (int p = 0; p < 4; p++) {
        float2 c[8];
        #pragma unroll
        for (int j = 0; j < 8; j++) c[j] = unpack2(acc2[p][j]);
        #pragma unroll
        for (int half = 0; half < 2; half++) {
            long row = i0 + ty * 8 + 2 * p + half;
            #pragma unroll
            for (int jq = 0; jq < 2; jq++) {
                int col = j0 + tx * 8 + jq * 4;
                float4 v;
                v.x = alpha * (half ? c[jq*4+0].y : c[jq*4+0].x);
                v.y = alpha * (half ? c[jq*4+1].y : c[jq*4+1].x);
                v.z = alpha * (half ? c[jq*4+2].y : c[jq*4+2].x);
                v.w = alpha * (half ? c[jq*4+3].y : c[jq*4+3].x);
                if (bias) {
                    v.x += bias[col + 0]; v.y += bias[col + 1];
                    v.z += bias[col + 2]; v.w += bias[col + 3];
                }
                *(float4*)&C[row * N + col] = v;
            }
        }
    }
}

// ---------------- batched 64x64-tile GEMM, f32x2, high occupancy ----------------
// TRANSA=0: A(i,k)=A[i*lda+k]; TRANSA=1: A(i,k)=A[k*lda+i]. B(k,j)=B[k*ldb+j].
// C(i,j) = alpha*acc + beta*D(i,j). grid (N/64, M/64, nbatch). K%8==0.
// 256 threads: 128 load A, 128 load B; compute 4 rows x 4 cols per thread.
template<int TRANSA>
__global__ __launch_bounds__(256) void gemm64_kernel(
    const float* __restrict__ A, const float* __restrict__ B,
    const float* __restrict__ D, float* __restrict__ C,
    int K, int lda, int ldb, int ldc,
    long sAo, long sAi, long sBo, long sBi, long sDo, long sDi, long sCo, long sCi,
    float alpha, float beta)
{
    int z = blockIdx.z; int zb = z >> 3, zh = z & 7;
    A += zb * sAo + zh * sAi;
    B += zb * sBo + zh * sBi;
    C += zb * sCo + zh * sCi;
    if (D) D += zb * sDo + zh * sDi;

    __shared__ float As[2][8][68];
    __shared__ float Bs[2][8][68];

    int tid = threadIdx.x;
    int ty = tid >> 4, tx = tid & 15;
    int i0 = blockIdx.y * 64, j0 = blockIdx.x * 64;

    bool isA = tid < 128;
    int lt = tid & 127;
    int l_k  = lt >> 4;            // 0..7
    int l_q4 = (lt & 15) * 4;      // 0..60
    int a_row = lt >> 1;           // 0..63 (TRANSA=0)
    int a_kq  = (lt & 1) * 4;      // 0 or 4

    const float* Lptr;
    long lstride;
    if (isA) {
        if (TRANSA) { Lptr = A + (long)l_k * lda + i0 + l_q4; lstride = 8L * lda; }
        else        { Lptr = A + (long)(i0 + a_row) * lda + a_kq; lstride = 8; }
    } else {
        Lptr = B + (long)l_k * ldb + j0 + l_q4; lstride = 8L * ldb;
    }

    float4 lv = *(const float4*)Lptr;
    if (isA) {
        if (TRANSA) *(float4*)&As[0][l_k][l_q4] = lv;
        else {
            As[0][a_kq + 0][a_row] = lv.x; As[0][a_kq + 1][a_row] = lv.y;
            As[0][a_kq + 2][a_row] = lv.z; As[0][a_kq + 3][a_row] = lv.w;
        }
    } else {
        *(float4*)&Bs[0][l_k][l_q4] = lv;
    }
    __syncthreads();

    u64 acc2[2][4] = {};    // 2 row-pairs x 4 cols
    int T = K / 8;
    int buf = 0;
    for (int t = 0; t < T; t++) {
        if (t + 1 < T) lv = *(const float4*)(Lptr + (long)(t + 1) * lstride);
        #pragma unroll
        for (int kk = 0; kk < 8; kk++) {
            ulonglong2 ap = *(const ulonglong2*)&As[buf][kk][ty * 4];
            float4 b0 = *(const float4*)&Bs[buf][kk][tx * 4];
            u64 bd0 = dup2(b0.x), bd1 = dup2(b0.y), bd2 = dup2(b0.z), bd3 = dup2(b0.w);
            ffma2(acc2[0][0], ap.x, bd0); ffma2(acc2[0][1], ap.x, bd1);
            ffma2(acc2[0][2], ap.x, bd2); ffma2(acc2[0][3], ap.x, bd3);
            ffma2(acc2[1][0], ap.y, bd0); ffma2(acc2[1][1], ap.y, bd1);
            ffma2(acc2[1][2], ap.y, bd2); ffma2(acc2[1][3], ap.y, bd3);
        }
        if (t + 1 < T) {
            int nb = buf ^ 1;
            if (isA) {
                if (TRANSA) *(float4*)&As[nb][l_k][l_q4] = lv;
                else {
                    As[nb][a_kq + 0][a_row] = lv.x; As[nb][a_kq + 1][a_row] = lv.y;
                    As[nb][a_kq + 2][a_row] = lv.z; As[nb][a_kq + 3][a_row] = lv.w;
                }
            } else {
                *(float4*)&Bs[nb][l_k][l_q4] = lv;
            }
            __syncthreads();
            buf = nb;
        }
    }

    #pragma unroll
    for (int p = 0; p < 2; p++) {
        float2 c0 = unpack2(acc2[p][0]);
        float2 c1 = unpack2(acc2[p][1]);
        float2 c2 = unpack2(acc2[p][2]);
        float2 c3 = unpack2(acc2[p][3]);
        #pragma unroll
        for (int half = 0; half < 2; half++) {
            long row = i0 + ty * 4 + 2 * p + half;
            long off = row * ldc + j0 + tx * 4;
            float4 v;
            v.x = alpha * (half ? c0.y : c0.x);
            v.y = alpha * (half ? c1.y : c1.x);
            v.z = alpha * (half ? c2.y : c2.x);
            v.w = alpha * (half ? c3.y : c3.x);
            if (D) {
                float4 dv = *(const float4*)&D[off];
                v.x += beta * dv.x; v.y += beta * dv.y;
                v.z += beta * dv.z; v.w += beta * dv.w;
            }
            *(float4*)&C[off] = v;
        }
    }
}

// ---------------- landmark pooling (writes TRANSPOSED klT[bh][d][m]) ----------------
__global__ void landmark_kernel(const float* __restrict__ kv, float* __restrict__ klT)
{
    int dd = threadIdx.x;
    int j  = blockIdx.x;
    int bh = blockIdx.y;
    int b = bh >> 3, h = bh & 7;
    const float* base = kv + (long)b * NN_ * 1024 + (long)(j * 16) * 1024 + h * DHv + dd;
    float s = 0.f;
    #pragma unroll
    for (int t = 0; t < 16; t++) s += base[(long)t * 1024];
    klT[((long)bh * DHv + dd) * LMv + j] = s;
}

// ---------------- row softmax over 256 columns (in place) ----------------
__global__ void softmax256_kernel(float* __restrict__ a)
{
    int row = blockIdx.x * 8 + (threadIdx.x >> 5);
    int lane = threadIdx.x & 31;
    float* p = a + (long)row * 256;
    float v[8];
    float mx = -1e30f;
    #pragma unroll
    for (int t = 0; t < 8; t++) { v[t] = p[lane + 32 * t]; mx = fmaxf(mx, v[t]); }
    #pragma unroll
    for (int o = 16; o > 0; o >>= 1) mx = fmaxf(mx, __shfl_xor_sync(0xffffffffu, mx, o));
    float s = 0.f;
    #pragma unroll
    for (int t = 0; t < 8; t++) { v[t] = __expf(v[t] - mx); s += v[t]; }
    #pragma unroll
    for (int o = 16; o > 0; o >>= 1) s += __shfl_xor_sync(0xffffffffu, s, o);
    float inv = 1.f / s;
    #pragma unroll
    for (int t = 0; t < 8; t++) p[lane + 32 * t] = v[t] * inv;
}

// ---------------- column sums of attn1 + global max ----------------
__global__ void initmax_kernel(float* m) { m[0] = 0.f; }

__global__ void colsummax_kernel(const float* __restrict__ a, float* __restrict__ dmax)
{
    int idx = blockIdx.x * blockDim.x + threadIdx.x;
    int bh = idx >> 8, j = idx & 255;
    const float* p = a + (long)bh * NQv * LMv + j;
    float s = 0.f;
    for (int i = 0; i < NQv; i++) s += p[(long)i * 256];
    atomicMax((int*)dmax, __float_as_int(s));
}

// ---------------- q0 = alpha * I ----------------
__global__ void qinit_kernel(float* __restrict__ q, const float* __restrict__ dmax)
{
    long idx = (long)blockIdx.x * 256 + threadIdx.x;
    int r = (int)((idx >> 8) & 255), c = (int)(idx & 255);
    q[idx] = (r == c) ? (1.0f / dmax[0]) : 0.f;
}

// ---------------- flash attention v4: 64q x 64k tiles, f32x2, high occupancy ------
// grid (NQ/64, 16), 256 threads, smem 4*64*68*4 = 69632 B (3 blocks/SM)
#define FLASH3_SMEM (4 * 64 * 68 * 4)
__global__ __launch_bounds__(256) void flash3_kernel(
    const float* __restrict__ qmat, const float* __restrict__ kv, float* __restrict__ Y)
{
    int bh = blockIdx.y; int b = bh >> 3, h = bh & 7;
    const float* qb = qmat + (long)b * NQv * INNER + h * DHv;
    const float* kb = kv + (long)b * NN_ * 1024 + h * DHv;
    const float* vb = kb + 512;
    int i0 = blockIdx.x * 64;

    extern __shared__ float sm[];
    float (*Qts)[68] = (float(*)[68])sm;               // [d][q]
    float (*Kts)[68] = (float(*)[68])(sm + 64 * 68);   // [d][c]
    float (*Vs)[68]  = (float(*)[68])(sm + 2 * 64 * 68); // [c][d]
    float (*Ps)[68]  = (float(*)[68])(sm + 3 * 64 * 68); // [q][c]

    int tid = threadIdx.x, ty = tid >> 4, tx = tid & 15;
    int lr = tid >> 4;            // 0..15
    int ldq = (tid & 15) << 2;    // 0..60

    // Q tile: vector LDG + scalar transpose STS
    #pragma unroll
    for (int u = 0; u < 4; u++) {
        int r = u * 16 + lr;
        float4 f = *(const float4*)(qb + (long)(i0 + r) * INNER + ldq);
        Qts[ldq + 0][r] = f.x; Qts[ldq + 1][r] = f.y;
        Qts[ldq + 2][r] = f.z; Qts[ldq + 3][r] = f.w;
    }

    float m[4], l[4];
    u64 o2[4][2];
    #pragma unroll
    for (int i = 0; i < 4; i++) {
        m[i] = -1e30f; l[i] = 0.f;
        o2[i][0] = 0ull; o2[i][1] = 0ull;
    }

    for (int c0 = 0; c0 < NN_; c0 += 64) {
        #pragma unroll
        for (int u = 0; u < 4; u++) {
            int r = u * 16 + lr;
            float4 fk = *(const float4*)(kb + (long)(c0 + r) * 1024 + ldq);
            Kts[ldq + 0][r] = fk.x; Kts[ldq + 1][r] = fk.y;
            Kts[ldq + 2][r] = fk.z; Kts[ldq + 3][r] = fk.w;
            float4 fv = *(const float4*)(vb + (long)(c0 + r) * 1024 + ldq);
            *(float4*)&Vs[r][ldq] = fv;
        }
        __syncthreads();

        // S = Q^T K : 2 row-pairs x 4 cols
        u64 s2[2][4] = {};
        #pragma unroll
        for (int d = 0; d < 64; d++) {
            ulonglong2 ap = *(const ulonglong2*)&Qts[d][ty * 4];
            float4 b0 = *(const float4*)&Kts[d][tx * 4];
            u64 bd0 = dup2(b0.x), bd1 = dup2(b0.y), bd2 = dup2(b0.z), bd3 = dup2(b0.w);
            ffma2(s2[0][0], ap.x, bd0); ffma2(s2[0][1], ap.x, bd1);
            ffma2(s2[0][2], ap.x, bd2); ffma2(s2[0][3], ap.x, bd3);
            ffma2(s2[1][0], ap.y, bd0); ffma2(s2[1][1], ap.y, bd1);
            ffma2(s2[1][2], ap.y, bd2); ffma2(s2[1][3], ap.y, bd3);
        }

        // online softmax per row-pair
        #pragma unroll
        for (int p = 0; p < 2; p++) {
            int r0 = 2 * p, r1 = 2 * p + 1;
            float mx0 = -1e30f, mx1 = -1e30f;
            #pragma unroll
            for (int j = 0; j < 4; j++) {
                float2 f = unpack2(s2[p][j]);
                mx0 = fmaxf(mx0, f.x); mx1 = fmaxf(mx1, f.y);
            }
            #pragma unroll
            for (int off = 8; off > 0; off >>= 1) {
                mx0 = fmaxf(mx0, __shfl_xor_sync(0xffffffffu, mx0, off));
                mx1 = fmaxf(mx1, __shfl_xor_sync(0xffffffffu, mx1, off));
            }
            float mn0 = fmaxf(m[r0], mx0), mn1 = fmaxf(m[r1], mx1);
            float corr0 = __expf(m[r0] - mn0), corr1 = __expf(m[r1] - mn1);
            float rs0 = 0.f, rs1 = 0.f;
            #pragma unroll
            for (int j = 0; j < 4; j++) {
                float2 f = unpack2(s2[p][j]);
                float e0 = __expf(f.x - mn0);
                float e1 = __expf(f.y - mn1);
                rs0 += e0; rs1 += e1;
                Ps[ty * 4 + r0][tx * 4 + j] = e0;
                Ps[ty * 4 + r1][tx * 4 + j] = e1;
            }
            #pragma unroll
            for (int off = 8; off > 0; off >>= 1) {
                rs0 += __shfl_xor_sync(0xffffffffu, rs0, off);
                rs1 += __shfl_xor_sync(0xffffffffu, rs1, off);
            }
            l[r0] = l[r0] * corr0 + rs0;
            l[r1] = l[r1] * corr1 + rs1;
            u64 cd0 = dup2(corr0), cd1 = dup2(corr1);
            fmul2(o2[r0][0], cd0); fmul2(o2[r0][1], cd0);
            fmul2(o2[r1][0], cd1); fmul2(o2[r1][1], cd1);
            m[r0] = mn0; m[r1] = mn1;
        }
        __syncthreads();

        // O += P V
        #pragma unroll 4
        for (int c = 0; c < 64; c += 4) {
            ulonglong2 v0 = *(const ulonglong2*)&Vs[c + 0][tx * 4];
            ulonglong2 v1 = *(const ulonglong2*)&Vs[c + 1][tx * 4];
            ulonglong2 v2 = *(const ulonglong2*)&Vs[c + 2][tx * 4];
            ulonglong2 v3 = *(const ulonglong2*)&Vs[c + 3][tx * 4];
            #pragma unroll
            for (int i = 0; i < 4; i++) {
                float4 p = *(const float4*)&Ps[ty * 4 + i][c];
                u64 pd;
                pd = dup2(p.x); ffma2(o2[i][0], pd, v0.x); ffma2(o2[i][1], pd, v0.y);
                pd = dup2(p.y); ffma2(o2[i][0], pd, v1.x); ffma2(o2[i][1], pd, v1.y);
                pd = dup2(p.z); ffma2(o2[i][0], pd, v2.x); ffma2(o2[i][1], pd, v2.y);
                pd = dup2(p.w); ffma2(o2[i][0], pd, v3.x); ffma2(o2[i][1], pd, v3.y);
            }
        }
        __syncthreads();
    }

    #pragma unroll
    for (int i = 0; i < 4; i++) {
        float inv = 1.f / l[i];
        float2 f0 = unpack2(o2[i][0]);
        float2 f1 = unpack2(o2[i][1]);
        float4 v = make_float4(f0.x * inv, f0.y * inv, f1.x * inv, f1.y * inv);
        *(float4*)&Y[((long)bh * NQv + (i0 + ty * 4 + i)) * DHv + tx * 4] = v;
    }
}

// ---------------- host launch ----------------
static void* sym(const void* s) { void* p = nullptr; cudaGetSymbolAddress(&p, s); return p; }

extern "C" void kernel_launch(void* const* d_in, const int* in_sizes, int n_in,
                              void* d_out, int out_size)
{
    const float* x      = (const float*)d_in[0];
    const float* qin    = (const float*)d_in[1];
    const float* W_kv   = (const float*)d_in[2];
    const float* W_q    = (const float*)d_in[3];
    const float* W_out  = (const float*)d_in[4];
    const float* b_out  = (const float*)d_in[5];
    float* out = (float*)d_out;

    float* kv    = (float*)sym(g_kv);
    float* qmat  = (float*)sym(g_qmat);
    float* klT   = (float*)sym(g_klT);
    float* attn1 = (float*)sym(g_attn1);
    float* G     = (float*)sym(g_G);
    float* qA    = (float*)sym(g_qA);
    float* qB    = (float*)sym(g_qB);
    float* Mb    = (float*)sym(g_M);
    float* r1    = (float*)sym(g_r1);
    float* r2    = (float*)sym(g_r2);
    float* Yb    = (float*)sym(g_Y);
    float* xty   = (float*)sym(g_xty);
    float* z2    = (float*)sym(g_z2);
    float* oc    = (float*)sym(g_oc);
    float* dmax  = (float*)sym(g_max);

    static bool init_done = false;
    static cudaStream_t s1;
    static cudaEvent_t eIn, eKV, eQ, eAttn, eY;
    if (!init_done) {
        cudaFuncSetAttribute(flash3_kernel, cudaFuncAttributeMaxDynamicSharedMemorySize, FLASH3_SMEM);
        cudaStreamCreateWithFlags(&s1, cudaStreamNonBlocking);
        cudaEventCreateWithFlags(&eIn,   cudaEventDisableTiming);
        cudaEventCreateWithFlags(&eKV,   cudaEventDisableTiming);
        cudaEventCreateWithFlags(&eQ,    cudaEventDisableTiming);
        cudaEventCreateWithFlags(&eAttn, cudaEventDisableTiming);
        cudaEventCreateWithFlags(&eY,    cudaEventDisableTiming);
        init_done = true;
    }

    const float scale = 0.125f;
    const long PQ = (long)LMv * LMv;
    const long A1 = (long)NQv * LMv;
    const long YS = (long)NQv * DHv;
    const long XS = (long)LMv * DHv;
    const long KLT = (long)DHv * LMv;

    // fork point
    cudaEventRecord(eIn, 0);
    cudaStreamWaitEvent(s1, eIn, 0);

    // launch #1  s0: kv = x @ W_kv
    sgemm128_kernel<<<dim3(1024/128, 8192/128, 1), 256, 0, 0>>>(
        x, W_kv, nullptr, kv, 8192, 1024, 512, 1.f);
    cudaEventRecord(eKV, 0);

    // launch #2  s1: qmat = scale * (q_input @ W_q)
    sgemm128_kernel<<<dim3(512/128, 2048/128, 1), 256, 0, s1>>>(
        qin, W_q, nullptr, qmat, 2048, 512, 512, scale);
    cudaEventRecord(eQ, s1);

    // launch #3  s0: landmarks (transposed output)
    landmark_kernel<<<dim3(256, 16), 64, 0, 0>>>(kv, klT);

    // launch #4  s1: flash (waits kv) — positioned for ncu profiling
    cudaStreamWaitEvent(s1, eKV, 0);
    flash3_kernel<<<dim3(NQv / 64, 16), 256, FLASH3_SMEM, s1>>>(qmat, kv, Yb);

    // launch #5  s0: sim1 = q @ klT  (needs qmat + landmarks)
    cudaStreamWaitEvent(0, eQ, 0);
    gemm64_kernel<0><<<dim3(4, 16, 16), 256, 0, 0>>>(
        qmat, klT, nullptr, attn1, 64, 512, 256, 256,
        (long)NQv*INNER, 64, 8*KLT, KLT, 0,0, 8*A1, A1, 1.f, 0.f);

    // launch #6  s0: softmax
    softmax256_kernel<<<(BHv * NQv) / 8, 256, 0, 0>>>(attn1);
    cudaEventRecord(eAttn, 0);

    // s1: xty = attn1^T @ Y (after flash; waits attn1)
    cudaStreamWaitEvent(s1, eAttn, 0);
    gemm64_kernel<1><<<dim3(1, 4, 16), 256, 0, s1>>>(
        attn1, Yb, nullptr, xty, 1024, 256, 64, 64,
        8*A1, A1, 8*YS, YS, 0,0, 8*XS, XS, 1.f, 0.f);
    cudaEventRecord(eY, s1);

    // ---- s0 branch: G + alpha + pinv chain ----
    gemm64_kernel<1><<<dim3(4, 4, 16), 256, 0, 0>>>(
        attn1, attn1, nullptr, G, 1024, 256, 256, 256,
        8*A1, A1, 8*A1, A1, 0,0, 8*PQ, PQ, 1.f, 0.f);

    initmax_kernel<<<1, 1, 0, 0>>>(dmax);
    colsummax_kernel<<<16, 256, 0, 0>>>(attn1, dmax);
    qinit_kernel<<<(BHv * 256 * 256) / 256, 256, 0, 0>>>(qA, dmax);

    float* qc = qA; float* qn = qB;
    for (int it = 0; it < 6; it++) {
        gemm64_kernel<0><<<dim3(4, 4, 16), 256, 0, 0>>>(
            qc, G, nullptr, Mb, 256, 256, 256, 256,
            8*PQ, PQ, 8*PQ, PQ, 0,0, 8*PQ, PQ, 1.f, 0.f);
        gemm64_kernel<0><<<dim3(4, 4, 16), 256, 0, 0>>>(
            Mb, qc, qc, r1, 256, 256, 256, 256,
            8*PQ, PQ, 8*PQ, PQ, 8*PQ, PQ, 8*PQ, PQ, -1.f, 7.f);
        gemm64_kernel<0><<<dim3(4, 4, 16), 256, 0, 0>>>(
            Mb, r1, qc, r2, 256, 256, 256, 256,
            8*PQ, PQ, 8*PQ, PQ, 8*PQ, PQ, 8*PQ, PQ, -1.f, 15.f);
        gemm64_kernel<0><<<dim3(4, 4, 16), 256, 0, 0>>>(
            Mb, r2, qc, qn, 256, 256, 256, 256,
            8*PQ, PQ, 8*PQ, PQ, 8*PQ, PQ, 8*PQ, PQ, -0.25f, 3.25f);
        float* t = qc; qc = qn; qn = t;
    }

    // join
    cudaStreamWaitEvent(0, eY, 0);

    gemm64_kernel<0><<<dim3(1, 4, 16), 256, 0, 0>>>(
        qc, xty, nullptr, z2, 256, 256, 64, 64,
        8*PQ, PQ, 8*XS, XS, 0,0, 8*XS, XS, 1.f, 0.f);

    gemm64_kernel<0><<<dim3(1, 16, 16), 256, 0, 0>>>(
        attn1, z2, nullptr, oc, 256, 256, 64, 512,
        8*A1, A1, 8*XS, XS, 0,0, (long)NQv*INNER, 64, 1.f, 0.f);

    sgemm128_kernel<<<dim3(512/128, 2048/128, 1), 256, 0, 0>>>(
        oc, W_out, b_out, out, 2048, 512, 512, 1.f);
}

// round 10
// speedup vs baseline: 1.1129x; 1.0125x over previous
#include <cuda_runtime.h>
#include <cuda_bf16.h>

// Problem constants
#define BB   2
#define NN_  4096
#define NQv  1024
#define DIMv 512
#define HH   8
#define DHv  64
#define LMv  256
#define BHv  16
#define INNER 512

typedef unsigned long long u64;

// ---------------- f32x2 packed helpers (Blackwell) ----------------
__device__ __forceinline__ void ffma2(u64 &d, u64 a, u64 b) {
    asm("fma.rn.f32x2 %0, %1, %2, %0;" : "+l"(d) : "l"(a), "l"(b));
}
__device__ __forceinline__ u64 pack2(float x, float y) {
    u64 r; asm("mov.b64 %0, {%1, %2};" : "=l"(r) : "f"(x), "f"(y)); return r;
}
__device__ __forceinline__ u64 dup2(float x) { return pack2(x, x); }
__device__ __forceinline__ float2 unpack2(u64 v) {
    float lo, hi; asm("mov.b64 {%0, %1}, %2;" : "=f"(lo), "=f"(hi) : "l"(v));
    return make_float2(lo, hi);
}
__device__ __forceinline__ void fmul2(u64 &d, u64 a) {
    asm("mul.rn.f32x2 %0, %0, %1;" : "+l"(d) : "l"(a));
}

// ---------------- scratch (device globals; no allocation allowed) ----------------
__device__ float g_kv[(long)BB*NN_*1024];
__device__ float g_qmat[(long)BB*NQv*INNER];
__device__ float g_klT[BHv*DHv*LMv];           // landmarks TRANSPOSED (bh, 64, 256)
__device__ float g_attn1[(long)BHv*NQv*LMv];
__device__ float g_G[BHv*LMv*LMv];
__device__ float g_qA[BHv*LMv*LMv];
__device__ float g_qB[BHv*LMv*LMv];
__device__ float g_M[BHv*LMv*LMv];
__device__ float g_r1[BHv*LMv*LMv];
__device__ float g_r2[BHv*LMv*LMv];
__device__ float g_Y[BHv*NQv*DHv];
__device__ float g_xty[BHv*LMv*DHv];
__device__ float g_z2[BHv*LMv*DHv];
__device__ float g_oc[(long)BB*NQv*INNER];
__device__ float g_max[1];

// ---------------- 128x128 SGEMM, f32x2 accumulators (big contiguous GEMMs) -------
__global__ __launch_bounds__(256) void sgemm128_kernel(
    const float* __restrict__ A, const float* __restrict__ B,
    const float* __restrict__ bias, float* __restrict__ C,
    int M, int N, int K, float alpha)
{
    __shared__ float As[2][8][132];
    __shared__ float Bs[2][8][128];

    int tid = threadIdx.x;
    int ty = tid >> 4, tx = tid & 15;
    int i0 = blockIdx.y * 128, j0 = blockIdx.x * 128;

    int arow = tid >> 1, akq = (tid & 1) * 4;
    int bkr = tid >> 5, bcq = (tid & 31) * 4;

    const float* Aptr = A + (long)(i0 + arow) * K + akq;
    const float* Bptr = B + (long)bkr * N + j0 + bcq;

    float4 av = *(const float4*)Aptr;
    float4 bv = *(const float4*)Bptr;
    As[0][akq + 0][arow] = av.x; As[0][akq + 1][arow] = av.y;
    As[0][akq + 2][arow] = av.z; As[0][akq + 3][arow] = av.w;
    *(float4*)&Bs[0][bkr][bcq] = bv;
    __syncthreads();

    u64 acc2[4][8] = {};
    int T = K / 8;
    int buf = 0;
    for (int t = 0; t < T; t++) {
        if (t + 1 < T) {
            av = *(const float4*)(Aptr + (t + 1) * 8);
            bv = *(const float4*)(Bptr + (long)(t + 1) * 8 * N);
        }
        #pragma unroll
        for (int kk = 0; kk < 8; kk++) {
            ulonglong2 a01 = *(const ulonglong2*)&As[buf][kk][ty * 8];
            ulonglong2 a23 = *(const ulonglong2*)&As[buf][kk][ty * 8 + 4];
            float4 b0 = *(const float4*)&Bs[buf][kk][tx * 8];
            float4 b1 = *(const float4*)&Bs[buf][kk][tx * 8 + 4];
            u64 ap[4] = {a01.x, a01.y, a23.x, a23.y};
            u64 bd[8] = {dup2(b0.x), dup2(b0.y), dup2(b0.z), dup2(b0.w),
                         dup2(b1.x), dup2(b1.y), dup2(b1.z), dup2(b1.w)};
            #pragma unroll
            for (int p = 0; p < 4; p++)
                #pragma unroll
                for (int j = 0; j < 8; j++)
                    ffma2(acc2[p][j], ap[p], bd[j]);
        }
        if (t + 1 < T) {
            int nb = buf ^ 1;
            As[nb][akq + 0][arow] = av.x; As[nb][akq + 1][arow] = av.y;
            As[nb][akq + 2][arow] = av.z; As[nb][akq + 3][arow] = av.w;
            *(float4*)&Bs[nb][bkr][bcq] = bv;
            __syncthreads();
            buf = nb;
        }
    }

    #pragma unroll
    for (int p = 0; p < 4; p++) {
        float2 c[8];
        #pragma unroll
        for (int j = 0; j < 8; j++) c[j] = unpack2(acc2[p][j]);
        #pragma unroll
        for (int half = 0; half < 2; half++) {
            long row = i0 + ty * 8 + 2 * p + half;
            #pragma unroll
            for (int jq = 0; jq < 2; jq++) {
                int col = j0 + tx * 8 + jq * 4;
                float4 v;
                v.x = alpha * (half ? c[jq*4+0].y : c[jq*4+0].x);
                v.y = alpha * (half ? c[jq*4+1].y : c[jq*4+1].x);
                v.z = alpha * (half ? c[jq*4+2].y : c[jq*4+2].x);
                v.w = alpha * (half ? c[jq*4+3].y : c[jq*4+3].x);
                if (bias) {
                    v.x += bias[col + 0]; v.y += bias[col + 1];
                    v.z += bias[col + 2]; v.w += bias[col + 3];
                }
                *(float4*)&C[row * N + col] = v;
            }
        }
    }
}

// ---------------- batched 64x64-tile GEMM, f32x2, high occupancy ----------------
template<int TRANSA>
__global__ __launch_bounds__(256) void gemm64_kernel(
    const float* __restrict__ A, const float* __restrict__ B,
    const float* __restrict__ D, float* __restrict__ C,
    int K, int lda, int ldb, int ldc,
    long sAo, long sAi, long sBo, long sBi, long sDo, long sDi, long sCo, long sCi,
    float alpha, float beta)
{
    int z = blockIdx.z; int zb = z >> 3, zh = z & 7;
    A += zb * sAo + zh * sAi;
    B += zb * sBo + zh * sBi;
    C += zb * sCo + zh * sCi;
    if (D) D += zb * sDo + zh * sDi;

    __shared__ float As[2][8][68];
    __shared__ float Bs[2][8][68];

    int tid = threadIdx.x;
    int ty = tid >> 4, tx = tid & 15;
    int i0 = blockIdx.y * 64, j0 = blockIdx.x * 64;

    bool isA = tid < 128;
    int lt = tid & 127;
    int l_k  = lt >> 4;            // 0..7
    int l_q4 = (lt & 15) * 4;      // 0..60
    int a_row = lt >> 1;           // 0..63 (TRANSA=0)
    int a_kq  = (lt & 1) * 4;      // 0 or 4

    const float* Lptr;
    long lstride;
    if (isA) {
        if (TRANSA) { Lptr = A + (long)l_k * lda + i0 + l_q4; lstride = 8L * lda; }
        else        { Lptr = A + (long)(i0 + a_row) * lda + a_kq; lstride = 8; }
    } else {
        Lptr = B + (long)l_k * ldb + j0 + l_q4; lstride = 8L * ldb;
    }

    float4 lv = *(const float4*)Lptr;
    if (isA) {
        if (TRANSA) *(float4*)&As[0][l_k][l_q4] = lv;
        else {
            As[0][a_kq + 0][a_row] = lv.x; As[0][a_kq + 1][a_row] = lv.y;
            As[0][a_kq + 2][a_row] = lv.z; As[0][a_kq + 3][a_row] = lv.w;
        }
    } else {
        *(float4*)&Bs[0][l_k][l_q4] = lv;
    }
    __syncthreads();

    u64 acc2[2][4] = {};    // 2 row-pairs x 4 cols
    int T = K / 8;
    int buf = 0;
    for (int t = 0; t < T; t++) {
        if (t + 1 < T) lv = *(const float4*)(Lptr + (long)(t + 1) * lstride);
        #pragma unroll
        for (int kk = 0; kk < 8; kk++) {
            ulonglong2 ap = *(const ulonglong2*)&As[buf][kk][ty * 4];
            float4 b0 = *(const float4*)&Bs[buf][kk][tx * 4];
            u64 bd0 = dup2(b0.x), bd1 = dup2(b0.y), bd2 = dup2(b0.z), bd3 = dup2(b0.w);
            ffma2(acc2[0][0], ap.x, bd0); ffma2(acc2[0][1], ap.x, bd1);
            ffma2(acc2[0][2], ap.x, bd2); ffma2(acc2[0][3], ap.x, bd3);
            ffma2(acc2[1][0], ap.y, bd0); ffma2(acc2[1][1], ap.y, bd1);
            ffma2(acc2[1][2], ap.y, bd2); ffma2(acc2[1][3], ap.y, bd3);
        }
        if (t + 1 < T) {
            int nb = buf ^ 1;
            if (isA) {
                if (TRANSA) *(float4*)&As[nb][l_k][l_q4] = lv;
                else {
                    As[nb][a_kq + 0][a_row] = lv.x; As[nb][a_kq + 1][a_row] = lv.y;
                    As[nb][a_kq + 2][a_row] = lv.z; As[nb][a_kq + 3][a_row] = lv.w;
                }
            } else {
                *(float4*)&Bs[nb][l_k][l_q4] = lv;
            }
            __syncthreads();
            buf = nb;
        }
    }

    #pragma unroll
    for (int p = 0; p < 2; p++) {
        float2 c0 = unpack2(acc2[p][0]);
        float2 c1 = unpack2(acc2[p][1]);
        float2 c2 = unpack2(acc2[p][2]);
        float2 c3 = unpack2(acc2[p][3]);
        #pragma unroll
        for (int half = 0; half < 2; half++) {
            long row = i0 + ty * 4 + 2 * p + half;
            long off = row * ldc + j0 + tx * 4;
            float4 v;
            v.x = alpha * (half ? c0.y : c0.x);
            v.y = alpha * (half ? c1.y : c1.x);
            v.z = alpha * (half ? c2.y : c2.x);
            v.w = alpha * (half ? c3.y : c3.x);
            if (D) {
                float4 dv = *(const float4*)&D[off];
                v.x += beta * dv.x; v.y += beta * dv.y;
                v.z += beta * dv.z; v.w += beta * dv.w;
            }
            *(float4*)&C[off] = v;
        }
    }
}

// ---------------- landmark pooling (writes TRANSPOSED klT[bh][d][m]) ----------------
__global__ void landmark_kernel(const float* __restrict__ kv, float* __restrict__ klT)
{
    int dd = threadIdx.x;
    int j  = blockIdx.x;
    int bh = blockIdx.y;
    int b = bh >> 3, h = bh & 7;
    const float* base = kv + (long)b * NN_ * 1024 + (long)(j * 16) * 1024 + h * DHv + dd;
    float s = 0.f;
    #pragma unroll
    for (int t = 0; t < 16; t++) s += base[(long)t * 1024];
    klT[((long)bh * DHv + dd) * LMv + j] = s;
}

// ---------------- row softmax over 256 columns (in place) ----------------
__global__ void softmax256_kernel(float* __restrict__ a)
{
    int row = blockIdx.x * 8 + (threadIdx.x >> 5);
    int lane = threadIdx.x & 31;
    float* p = a + (long)row * 256;
    float v[8];
    float mx = -1e30f;
    #pragma unroll
    for (int t = 0; t < 8; t++) { v[t] = p[lane + 32 * t]; mx = fmaxf(mx, v[t]); }
    #pragma unroll
    for (int o = 16; o > 0; o >>= 1) mx = fmaxf(mx, __shfl_xor_sync(0xffffffffu, mx, o));
    float s = 0.f;
    #pragma unroll
    for (int t = 0; t < 8; t++) { v[t] = __expf(v[t] - mx); s += v[t]; }
    #pragma unroll
    for (int o = 16; o > 0; o >>= 1) s += __shfl_xor_sync(0xffffffffu, s, o);
    float inv = 1.f / s;
    #pragma unroll
    for (int t = 0; t < 8; t++) p[lane + 32 * t] = v[t] * inv;
}

// ---------------- column sums of attn1 + global max ----------------
__global__ void initmax_kernel(float* m) { m[0] = 0.f; }

__global__ void colsummax_kernel(const float* __restrict__ a, float* __restrict__ dmax)
{
    int idx = blockIdx.x * blockDim.x + threadIdx.x;
    int bh = idx >> 8, j = idx & 255;
    const float* p = a + (long)bh * NQv * LMv + j;
    float s = 0.f;
    for (int i = 0; i < NQv; i++) s += p[(long)i * 256];
    atomicMax((int*)dmax, __float_as_int(s));
}

// ---------------- q0 = alpha * I ----------------
__global__ void qinit_kernel(float* __restrict__ q, const float* __restrict__ dmax)
{
    long idx = (long)blockIdx.x * 256 + threadIdx.x;
    int r = (int)((idx >> 8) & 255), c = (int)(idx & 255);
    q[idx] = (r == c) ? (1.0f / dmax[0]) : 0.f;
}

// ---------------- flash attention: 128q x 128k tiles, f32x2, 8x8 S-tile ----------
// grid (NQ/128, 16), 256 threads, smem 169984 B (1 block/SM)
#define FLASH2_SMEM ((2*64*132 + 128*68 + 128*132) * 4)
__global__ __launch_bounds__(256) void flash2_kernel(
    const float* __restrict__ qmat, const float* __restrict__ kv, float* __restrict__ Y)
{
    int bh = blockIdx.y; int b = bh >> 3, h = bh & 7;
    const float* qb = qmat + (long)b * NQv * INNER + h * DHv;
    const float* kb = kv + (long)b * NN_ * 1024 + h * DHv;
    const float* vb = kb + 512;
    int i0 = blockIdx.x * 128;

    extern __shared__ float sm[];
    float (*Qts)[132] = (float(*)[132])sm;
    float (*Kts)[132] = (float(*)[132])(sm + 64 * 132);
    float (*Vs)[68]   = (float(*)[68]) (sm + 2 * 64 * 132);
    float (*Ps)[132]  = (float(*)[132])(sm + 2 * 64 * 132 + 128 * 68);

    int tid = threadIdx.x, ty = tid >> 4, tx = tid & 15;
    int lr = tid >> 4;            // 0..15
    int ldq = (tid & 15) << 2;    // 0..60

    // Q tile: vector LDG + scalar transpose STS
    #pragma unroll
    for (int u = 0; u < 8; u++) {
        int r = u * 16 + lr;
        float4 f = *(const float4*)(qb + (long)(i0 + r) * INNER + ldq);
        Qts[ldq + 0][r] = f.x; Qts[ldq + 1][r] = f.y;
        Qts[ldq + 2][r] = f.z; Qts[ldq + 3][r] = f.w;
    }

    float m[8], l[8];
    u64 o2[8][2];
    #pragma unroll
    for (int i = 0; i < 8; i++) {
        m[i] = -1e30f; l[i] = 0.f;
        o2[i][0] = 0ull; o2[i][1] = 0ull;
    }

    for (int c0 = 0; c0 < NN_; c0 += 128) {
        // K + V tiles: vector LDG; K transposed scalar STS, V float4 STS
        #pragma unroll
        for (int u = 0; u < 8; u++) {
            int r = u * 16 + lr;
            float4 fk = *(const float4*)(kb + (long)(c0 + r) * 1024 + ldq);
            Kts[ldq + 0][r] = fk.x; Kts[ldq + 1][r] = fk.y;
            Kts[ldq + 2][r] = fk.z; Kts[ldq + 3][r] = fk.w;
            float4 fv = *(const float4*)(vb + (long)(c0 + r) * 1024 + ldq);
            *(float4*)&Vs[r][ldq] = fv;
        }
        __syncthreads();

        // S = Q^T K : 4 row-pairs x 8 cols, f32x2 (0.5 B/FLOP)
        u64 s2[4][8] = {};
        #pragma unroll
        for (int d = 0; d < 64; d++) {
            ulonglong2 a01 = *(const ulonglong2*)&Qts[d][ty * 8];
            ulonglong2 a23 = *(const ulonglong2*)&Qts[d][ty * 8 + 4];
            float4 b0 = *(const float4*)&Kts[d][tx * 8];
            float4 b1 = *(const float4*)&Kts[d][tx * 8 + 4];
            u64 ap[4] = {a01.x, a01.y, a23.x, a23.y};
            u64 bd[8] = {dup2(b0.x), dup2(b0.y), dup2(b0.z), dup2(b0.w),
                         dup2(b1.x), dup2(b1.y), dup2(b1.z), dup2(b1.w)};
            #pragma unroll
            for (int p = 0; p < 4; p++)
                #pragma unroll
                for (int j = 0; j < 8; j++)
                    ffma2(s2[p][j], ap[p], bd[j]);
        }

        // online softmax per row-pair, directly from packed s2 (low reg pressure)
        #pragma unroll
        for (int p = 0; p < 4; p++) {
            int r0 = 2 * p, r1 = 2 * p + 1;
            float mx0 = -1e30f, mx1 = -1e30f;
            #pragma unroll
            for (int j = 0; j < 8; j++) {
                float2 f = unpack2(s2[p][j]);
                mx0 = fmaxf(mx0, f.x); mx1 = fmaxf(mx1, f.y);
            }
            #pragma unroll
            for (int off = 8; off > 0; off >>= 1) {
                mx0 = fmaxf(mx0, __shfl_xor_sync(0xffffffffu, mx0, off));
                mx1 = fmaxf(mx1, __shfl_xor_sync(0xffffffffu, mx1, off));
            }
            float mn0 = fmaxf(m[r0], mx0), mn1 = fmaxf(m[r1], mx1);
            float corr0 = __expf(m[r0] - mn0), corr1 = __expf(m[r1] - mn1);
            float rs0 = 0.f, rs1 = 0.f;
            #pragma unroll
            for (int j = 0; j < 8; j++) {
                float2 f = unpack2(s2[p][j]);
                float e0 = __expf(f.x - mn0);
                float e1 = __expf(f.y - mn1);
                rs0 += e0; rs1 += e1;
                Ps[ty * 8 + r0][tx * 8 + j] = e0;
                Ps[ty * 8 + r1][tx * 8 + j] = e1;
            }
            #pragma unroll
            for (int off = 8; off > 0; off >>= 1) {
                rs0 += __shfl_xor_sync(0xffffffffu, rs0, off);
                rs1 += __shfl_xor_sync(0xffffffffu, rs1, off);
            }
            l[r0] = l[r0] * corr0 + rs0;
            l[r1] = l[r1] * corr1 + rs1;
            u64 cd0 = dup2(corr0), cd1 = dup2(corr1);
            fmul2(o2[r0][0], cd0); fmul2(o2[r0][1], cd0);
            fmul2(o2[r1][0], cd1); fmul2(o2[r1][1], cd1);
            m[r0] = mn0; m[r1] = mn1;
        }
        __syncthreads();

        // O += P V : f32x2
        #pragma unroll 4
        for (int c = 0; c < 128; c += 4) {
            ulonglong2 v0 = *(const ulonglong2*)&Vs[c + 0][tx * 4];
            ulonglong2 v1 = *(const ulonglong2*)&Vs[c + 1][tx * 4];
            ulonglong2 v2 = *(const ulonglong2*)&Vs[c + 2][tx * 4];
            ulonglong2 v3 = *(const ulonglong2*)&Vs[c + 3][tx * 4];
            #pragma unroll
            for (int i = 0; i < 8; i++) {
                float4 p = *(const float4*)&Ps[ty * 8 + i][c];
                u64 pd;
                pd = dup2(p.x); ffma2(o2[i][0], pd, v0.x); ffma2(o2[i][1], pd, v0.y);
                pd = dup2(p.y); ffma2(o2[i][0], pd, v1.x); ffma2(o2[i][1], pd, v1.y);
                pd = dup2(p.z); ffma2(o2[i][0], pd, v2.x); ffma2(o2[i][1], pd, v2.y);
                pd = dup2(p.w); ffma2(o2[i][0], pd, v3.x); ffma2(o2[i][1], pd, v3.y);
            }
        }
        __syncthreads();
    }

    #pragma unroll
    for (int i = 0; i < 8; i++) {
        float inv = 1.f / l[i];
        float2 f0 = unpack2(o2[i][0]);
        float2 f1 = unpack2(o2[i][1]);
        float4 v = make_float4(f0.x * inv, f0.y * inv, f1.x * inv, f1.y * inv);
        *(float4*)&Y[((long)bh * NQv + (i0 + ty * 8 + i)) * DHv + tx * 4] = v;
    }
}

// ---------------- host launch ----------------
static void* sym(const void* s) { void* p = nullptr; cudaGetSymbolAddress(&p, s); return p; }

extern "C" void kernel_launch(void* const* d_in, const int* in_sizes, int n_in,
                              void* d_out, int out_size)
{
    const float* x      = (const float*)d_in[0];
    const float* qin    = (const float*)d_in[1];
    const float* W_kv   = (const float*)d_in[2];
    const float* W_q    = (const float*)d_in[3];
    const float* W_out  = (const float*)d_in[4];
    const float* b_out  = (const float*)d_in[5];
    float* out = (float*)d_out;

    float* kv    = (float*)sym(g_kv);
    float* qmat  = (float*)sym(g_qmat);
    float* klT   = (float*)sym(g_klT);
    float* attn1 = (float*)sym(g_attn1);
    float* G     = (float*)sym(g_G);
    float* qA    = (float*)sym(g_qA);
    float* qB    = (float*)sym(g_qB);
    float* Mb    = (float*)sym(g_M);
    float* r1    = (float*)sym(g_r1);
    float* r2    = (float*)sym(g_r2);
    float* Yb    = (float*)sym(g_Y);
    float* xty   = (float*)sym(g_xty);
    float* z2    = (float*)sym(g_z2);
    float* oc    = (float*)sym(g_oc);
    float* dmax  = (float*)sym(g_max);

    static bool init_done = false;
    static cudaStream_t s1;
    static cudaEvent_t eIn, eKV, eQ, eAttn, eY;
    if (!init_done) {
        cudaFuncSetAttribute(flash2_kernel, cudaFuncAttributeMaxDynamicSharedMemorySize, FLASH2_SMEM);
        cudaStreamCreateWithFlags(&s1, cudaStreamNonBlocking);
        cudaEventCreateWithFlags(&eIn,   cudaEventDisableTiming);
        cudaEventCreateWithFlags(&eKV,   cudaEventDisableTiming);
        cudaEventCreateWithFlags(&eQ,    cudaEventDisableTiming);
        cudaEventCreateWithFlags(&eAttn, cudaEventDisableTiming);
        cudaEventCreateWithFlags(&eY,    cudaEventDisableTiming);
        init_done = true;
    }

    const float scale = 0.125f;
    const long PQ = (long)LMv * LMv;
    const long A1 = (long)NQv * LMv;
    const long YS = (long)NQv * DHv;
    const long XS = (long)LMv * DHv;
    const long KLT = (long)DHv * LMv;

    // fork point
    cudaEventRecord(eIn, 0);
    cudaStreamWaitEvent(s1, eIn, 0);

    // launch #1  s0: kv = x @ W_kv
    sgemm128_kernel<<<dim3(1024/128, 8192/128, 1), 256, 0, 0>>>(
        x, W_kv, nullptr, kv, 8192, 1024, 512, 1.f);
    cudaEventRecord(eKV, 0);

    // launch #2  s1: qmat = scale * (q_input @ W_q)
    sgemm128_kernel<<<dim3(512/128, 2048/128, 1), 256, 0, s1>>>(
        qin, W_q, nullptr, qmat, 2048, 512, 512, scale);
    cudaEventRecord(eQ, s1);

    // launch #3  s0: landmarks (transposed output)
    landmark_kernel<<<dim3(256, 16), 64, 0, 0>>>(kv, klT);

    // launch #4  s1: flash (waits kv) — positioned for ncu profiling
    cudaStreamWaitEvent(s1, eKV, 0);
    flash2_kernel<<<dim3(NQv / 128, 16), 256, FLASH2_SMEM, s1>>>(qmat, kv, Yb);

    // launch #5  s0: sim1 = q @ klT  (needs qmat + landmarks)
    cudaStreamWaitEvent(0, eQ, 0);
    gemm64_kernel<0><<<dim3(4, 16, 16), 256, 0, 0>>>(
        qmat, klT, nullptr, attn1, 64, 512, 256, 256,
        (long)NQv*INNER, 64, 8*KLT, KLT, 0,0, 8*A1, A1, 1.f, 0.f);

    // launch #6  s0: softmax
    softmax256_kernel<<<(BHv * NQv) / 8, 256, 0, 0>>>(attn1);
    cudaEventRecord(eAttn, 0);

    // s1: xty = attn1^T @ Y (after flash; waits attn1)
    cudaStreamWaitEvent(s1, eAttn, 0);
    gemm64_kernel<1><<<dim3(1, 4, 16), 256, 0, s1>>>(
        attn1, Yb, nullptr, xty, 1024, 256, 64, 64,
        8*A1, A1, 8*YS, YS, 0,0, 8*XS, XS, 1.f, 0.f);
    cudaEventRecord(eY, s1);

    // ---- s0 branch: G + alpha + pinv chain ----
    gemm64_kernel<1><<<dim3(4, 4, 16), 256, 0, 0>>>(
        attn1, attn1, nullptr, G, 1024, 256, 256, 256,
        8*A1, A1, 8*A1, A1, 0,0, 8*PQ, PQ, 1.f, 0.f);

    initmax_kernel<<<1, 1, 0, 0>>>(dmax);
    colsummax_kernel<<<16, 256, 0, 0>>>(attn1, dmax);
    qinit_kernel<<<(BHv * 256 * 256) / 256, 256, 0, 0>>>(qA, dmax);

    float* qc = qA; float* qn = qB;
    for (int it = 0; it < 6; it++) {
        gemm64_kernel<0><<<dim3(4, 4, 16), 256, 0, 0>>>(
            qc, G, nullptr, Mb, 256, 256, 256, 256,
            8*PQ, PQ, 8*PQ, PQ, 0,0, 8*PQ, PQ, 1.f, 0.f);
        gemm64_kernel<0><<<dim3(4, 4, 16), 256, 0, 0>>>(
            Mb, qc, qc, r1, 256, 256, 256, 256,
            8*PQ, PQ, 8*PQ, PQ, 8*PQ, PQ, 8*PQ, PQ, -1.f, 7.f);
        gemm64_kernel<0><<<dim3(4, 4, 16), 256, 0, 0>>>(
            Mb, r1, qc, r2, 256, 256, 256, 256,
            8*PQ, PQ, 8*PQ, PQ, 8*PQ, PQ, 8*PQ, PQ, -1.f, 15.f);
        gemm64_kernel<0><<<dim3(4, 4, 16), 256, 0, 0>>>(
            Mb, r2, qc, qn, 256, 256, 256, 256,
            8*PQ, PQ, 8*PQ, PQ, 8*PQ, PQ, 8*PQ, PQ, -0.25f, 3.25f);
        float* t = qc; qc = qn; qn = t;
    }

    // join
    cudaStreamWaitEvent(0, eY, 0);

    gemm64_kernel<0><<<dim3(1, 4, 16), 256, 0, 0>>>(
        qc, xty, nullptr, z2, 256, 256, 64, 64,
        8*PQ, PQ, 8*XS, XS, 0,0, 8*XS, XS, 1.f, 0.f);

    gemm64_kernel<0><<<dim3(1, 16, 16), 256, 0, 0>>>(
        attn1, z2, nullptr, oc, 256, 256, 64, 512,
        8*A1, A1, 8*XS, XS, 0,0, (long)NQv*INNER, 64, 1.f, 0.f);

    sgemm128_kernel<<<dim3(512/128, 2048/128, 1), 256, 0, 0>>>(
        oc, W_out, b_out, out, 2048, 512, 512, 1.f);
}